// round 13
// baseline (speedup 1.0000x reference)
#include <cuda_runtime.h>
#include <math.h>

// ---------------- problem constants ----------------
#define Bg   32
#define NPG  2048
#define Nn   (Bg*NPG)        // 65536
#define Ee   (Nn*8)          // 524288
#define EPG  (Ee/Bg)         // 16384 edges per graph (contiguous per graph!)
#define IND  64
#define H1   128
#define H2   256
#define K1   1024
#define K2   512
#define N1   (Bg*K1)         // 32768
#define N2   (Bg*K2)         // 16384

#define AGG_BLOCKS 2368      // 16 CTAs/SM x 148 SMs, grid-stride

// ---------------- scratch (device globals; no allocs) ----------------
#define Z1_FLOATS (Nn*IND + Nn + 2*H1)
__device__ float g_z1[Z1_FLOATS];    // [agg1 | cnt1 | bnacc1]
#define Z2_FLOATS (N1*H1 + N1 + 2*H2)
__device__ float g_z2[Z2_FLOATS];    // [agg2 | cnt2 | bnacc2]

__device__ float g_pre1 [Nn*H1];
__device__ int   g_map1 [Nn];
__device__ int   g_src2 [Ee];
__device__ int   g_tgt2 [Ee];
__device__ float g_h1new[N1*H1];
__device__ float g_pre2 [N1*H2];
__device__ float g_rrel [Nn];
__device__ float g_rroot[Nn];
__device__ int   g_perm1[N1];
__device__ float g_tanh1[N1];
__device__ int   g_perm2[N2];
__device__ float g_tanh2[N2];
__device__ float g_scale[H2];
__device__ float g_shift[H2];
__device__ int   g_ctr1 = 0;
__device__ int   g_ctr2 = 0;

// ---------------- helpers ----------------
__device__ __forceinline__ unsigned long long pk2(float lo, float hi) {
    unsigned long long r;
    asm("mov.b64 %0, {%1,%2};" : "=l"(r) : "f"(lo), "f"(hi));
    return r;
}
__device__ __forceinline__ void upk2(unsigned long long v, float& lo, float& hi) {
    asm("mov.b64 {%0,%1}, %2;" : "=f"(lo), "=f"(hi) : "l"(v));
}
__device__ __forceinline__ void ffma2(unsigned long long& d, unsigned long long a, unsigned long long b) {
    asm("fma.rn.f32x2 %0, %1, %2, %0;" : "+l"(d) : "l"(a), "l"(b));
}

// ---------------- kernels ----------------

// grid-stride mean aggregation: one (edge, float4) work item per loop step
template<int D>
__global__ void agg_kernel(const int* __restrict__ src, const int* __restrict__ tgt,
                           const float* __restrict__ xin, float* __restrict__ aggo,
                           float* __restrict__ cnt, int nedges)
{
    const int V = D / 4;
    const int total = nedges * V;
    const int stride = gridDim.x * blockDim.x;
    for (int i = blockIdx.x * blockDim.x + threadIdx.x; i < total; i += stride) {
        int e  = i / V;
        int f4 = i - e * V;
        int s = src[e];
        if (s < 0) continue;
        int t = tgt[e];
        float4 v = reinterpret_cast<const float4*>(xin)[(size_t)s * V + f4];
        asm volatile("red.global.add.v4.f32 [%0], {%1,%2,%3,%4};"
                     :: "l"(&aggo[(size_t)t * D + f4 * 4]),
                        "f"(v.x), "f"(v.y), "f"(v.z), "f"(v.w) : "memory");
        if (f4 == 0) atomicAdd(&cnt[t], 1.0f);
    }
}

// pre[n,OD] = (agg[n]/max(cnt,1)) @ Wl + xin @ Wr + bias   (K concat, FFMA2)
// A read as packed ulonglong2 row-pairs (zero pack movs); W pre-duplicated in smem
// as (w,w) u64 pairs (zero broadcast movs). Both tiles prefetched one kt ahead.
// Epilogue: per-column sum/sumsq into bnacc; last block computes scale/shift.
template<int KD, int OD, int BM, int CG>
__global__ void __launch_bounds__(256)
gemm_dual6(const float* __restrict__ agg, const float* __restrict__ cnt,
           const float* __restrict__ xin,
           const float* __restrict__ Wl, const float* __restrict__ Wr,
           const float* __restrict__ bias, float* __restrict__ outp,
           float* __restrict__ bnacc, int* __restrict__ ctr,
           const float* __restrict__ bng, const float* __restrict__ bnb,
           float* __restrict__ scale, float* __restrict__ shift,
           float invn)
{
    const int TN = 8, BK = 32, ASTR = BM + 4;
    const int NTY = 256 / CG;
    const int NK  = 2 * KD / BK;
    const int ALD = BM * BK / (4 * 256);
    const int WLD = BK * OD / (4 * 256);
    extern __shared__ float sh[];
    unsigned long long* sWd = (unsigned long long*)sh;   // BK*OD u64 (dup pairs)
    float* sA = sh + 2 * BK * OD;                        // BK*ASTR floats

    int tid = threadIdx.x;
    int tx  = tid % CG;
    int ty  = tid / CG;
    int row0 = blockIdx.x * BM;

    unsigned long long acc[4][TN];
#pragma unroll
    for (int r = 0; r < 4; r++)
#pragma unroll
        for (int j = 0; j < TN; j++) acc[r][j] = 0ull;

    float4 areg[ALD];
    float  ainv[ALD];
    float4 wreg[WLD];

    // prefetch tile 0 (A and W)
#pragma unroll
    for (int j = 0; j < ALD; j++) {
        int idx = tid + j * 256;
        int m = idx >> 3, kq = idx & 7;
        int row = row0 + m;
        int kg = 4 * kq;
        if (kg < KD) {
            areg[j] = *reinterpret_cast<const float4*>(&agg[(size_t)row * KD + kg]);
            ainv[j] = 1.f / fmaxf(cnt[row], 1.f);
        } else {
            areg[j] = *reinterpret_cast<const float4*>(&xin[(size_t)row * KD + (kg - KD)]);
            ainv[j] = 1.f;
        }
    }
#pragma unroll
    for (int j = 0; j < WLD; j++) {
        int idx = tid + j * 256;
        int k = idx / (OD / 4), cq = idx % (OD / 4);
        wreg[j] = (k < KD) ? *reinterpret_cast<const float4*>(&Wl[(size_t)k * OD + 4 * cq])
                           : *reinterpret_cast<const float4*>(&Wr[(size_t)(k - KD) * OD + 4 * cq]);
    }

    for (int kti = 0; kti < NK; kti++) {
        __syncthreads();

        // STS A (transpose + mean-div)
#pragma unroll
        for (int j = 0; j < ALD; j++) {
            int idx = tid + j * 256;
            int m = idx >> 3, kq = idx & 7;
            float iv = ainv[j];
            sA[(4*kq+0) * ASTR + m] = areg[j].x * iv;
            sA[(4*kq+1) * ASTR + m] = areg[j].y * iv;
            sA[(4*kq+2) * ASTR + m] = areg[j].z * iv;
            sA[(4*kq+3) * ASTR + m] = areg[j].w * iv;
        }
        // STS W duplicated pairs
#pragma unroll
        for (int j = 0; j < WLD; j++) {
            int idx = tid + j * 256;
            int k = idx / (OD / 4), cq = idx % (OD / 4);
            unsigned long long* dst = &sWd[k * OD + 4 * cq];
            dst[0] = pk2(wreg[j].x, wreg[j].x);
            dst[1] = pk2(wreg[j].y, wreg[j].y);
            dst[2] = pk2(wreg[j].z, wreg[j].z);
            dst[3] = pk2(wreg[j].w, wreg[j].w);
        }

        // prefetch next tile
        if (kti + 1 < NK) {
            int ktn = (kti + 1) * BK;
#pragma unroll
            for (int j = 0; j < ALD; j++) {
                int idx = tid + j * 256;
                int m = idx >> 3, kq = idx & 7;
                int row = row0 + m;
                int kg = ktn + 4 * kq;
                if (kg < KD) {
                    areg[j] = *reinterpret_cast<const float4*>(&agg[(size_t)row * KD + kg]);
                    ainv[j] = 1.f / fmaxf(cnt[row], 1.f);
                } else {
                    areg[j] = *reinterpret_cast<const float4*>(&xin[(size_t)row * KD + (kg - KD)]);
                    ainv[j] = 1.f;
                }
            }
#pragma unroll
            for (int j = 0; j < WLD; j++) {
                int idx = tid + j * 256;
                int k = ktn + idx / (OD / 4), cq = idx % (OD / 4);
                wreg[j] = (k < KD) ? *reinterpret_cast<const float4*>(&Wl[(size_t)k * OD + 4 * cq])
                                   : *reinterpret_cast<const float4*>(&Wr[(size_t)(k - KD) * OD + 4 * cq]);
            }
        }

        __syncthreads();

#pragma unroll
        for (int k = 0; k < BK; k++) {
            const ulonglong2* ap2 = reinterpret_cast<const ulonglong2*>(&sA[k * ASTR + ty * 8]);
            ulonglong2 p0 = ap2[0], p1 = ap2[1];
            unsigned long long ap[4] = { p0.x, p0.y, p1.x, p1.y };
            const ulonglong2* wp2 = reinterpret_cast<const ulonglong2*>(&sWd[k * OD + tx * TN]);
            ulonglong2 q0 = wp2[0], q1 = wp2[1], q2 = wp2[2], q3 = wp2[3];
            unsigned long long w[8] = { q0.x, q0.y, q1.x, q1.y, q2.x, q2.y, q3.x, q3.y };
#pragma unroll
            for (int j = 0; j < TN; j++)
#pragma unroll
                for (int r = 0; r < 4; r++)
                    ffma2(acc[r][j], ap[r], w[j]);
        }
    }

    // epilogue: unpack, add bias, store; accumulate column stats
    float cs[TN], cs2[TN];
#pragma unroll
    for (int j = 0; j < TN; j++) { cs[j] = 0.f; cs2[j] = 0.f; }
    float bb[TN];
#pragma unroll
    for (int jj = 0; jj < TN / 4; jj++) {
        float4 b4 = *reinterpret_cast<const float4*>(&bias[tx * TN + jj * 4]);
        bb[jj*4+0]=b4.x; bb[jj*4+1]=b4.y; bb[jj*4+2]=b4.z; bb[jj*4+3]=b4.w;
    }
#pragma unroll
    for (int r = 0; r < 4; r++) {
        float lo[TN], hi[TN];
#pragma unroll
        for (int j = 0; j < TN; j++) {
            upk2(acc[r][j], lo[j], hi[j]);
            lo[j] += bb[j]; hi[j] += bb[j];
            cs[j]  += lo[j] + hi[j];
            cs2[j] += lo[j]*lo[j] + hi[j]*hi[j];
        }
        int row_lo = row0 + ty * 8 + 2 * r;
#pragma unroll
        for (int jj = 0; jj < TN / 4; jj++) {
            int c = tx * TN + jj * 4;
            *reinterpret_cast<float4*>(&outp[(size_t)row_lo * OD + c]) =
                make_float4(lo[jj*4], lo[jj*4+1], lo[jj*4+2], lo[jj*4+3]);
            *reinterpret_cast<float4*>(&outp[(size_t)(row_lo+1) * OD + c]) =
                make_float4(hi[jj*4], hi[jj*4+1], hi[jj*4+2], hi[jj*4+3]);
        }
    }

    // block-level stats reduce (reuse smem), then one atomic per column
    __syncthreads();
    float* sRed = sh;   // NTY*OD floats
#pragma unroll
    for (int j = 0; j < TN; j++) sRed[ty * OD + tx * TN + j] = cs[j];
    __syncthreads();
    for (int c = tid; c < OD; c += 256) {
        float t = 0.f;
#pragma unroll
        for (int i = 0; i < NTY; i++) t += sRed[i * OD + c];
        atomicAdd(&bnacc[c], t);
    }
    __syncthreads();
#pragma unroll
    for (int j = 0; j < TN; j++) sRed[ty * OD + tx * TN + j] = cs2[j];
    __syncthreads();
    for (int c = tid; c < OD; c += 256) {
        float t = 0.f;
#pragma unroll
        for (int i = 0; i < NTY; i++) t += sRed[i * OD + c];
        atomicAdd(&bnacc[OD + c], t);
    }

    __shared__ int sDone;
    __threadfence();
    if (tid == 0) {
        int old = atomicAdd(ctr, 1);
        sDone = (old == (int)gridDim.x - 1);
    }
    __syncthreads();
    if (sDone) {
        if (tid < OD) {
            float s  = __ldcg(&bnacc[tid]);
            float s2 = __ldcg(&bnacc[OD + tid]);
            float m   = s * invn;
            float var = s2 * invn - m * m;
            float sc  = rsqrtf(var + 1e-5f) * bng[tid];
            scale[tid] = sc;
            shift[tid] = bnb[tid] - m * sc;
        }
        if (tid == 0) *ctr = 0;
    }
}

// fused: BN apply (registers only) + ReLU + two score dot products. One warp per row.
template<int D>
__global__ void bnad_kernel(const float* __restrict__ pre, const float* __restrict__ scale,
                            const float* __restrict__ shift,
                            const float* __restrict__ wrel, const float* __restrict__ wroot,
                            float* __restrict__ rrel, float* __restrict__ rroot, int nrows)
{
    int w = (blockIdx.x * blockDim.x + threadIdx.x) >> 5;
    int lane = threadIdx.x & 31;
    if (w >= nrows) return;
    const int V = D / 128;
    float s1 = 0.f, s2 = 0.f;
    const float4* rowp = reinterpret_cast<const float4*>(pre + (size_t)w * D);
#pragma unroll
    for (int q = 0; q < V; q++) {
        int c4 = lane + q * 32;
        float4 v  = rowp[c4];
        float4 sc = reinterpret_cast<const float4*>(scale)[c4];
        float4 sh = reinterpret_cast<const float4*>(shift)[c4];
        v.x = fmaxf(fmaf(v.x, sc.x, sh.x), 0.f);
        v.y = fmaxf(fmaf(v.y, sc.y, sh.y), 0.f);
        v.z = fmaxf(fmaf(v.z, sc.z, sh.z), 0.f);
        v.w = fmaxf(fmaf(v.w, sc.w, sh.w), 0.f);
        float4 wr = reinterpret_cast<const float4*>(wrel)[c4];
        float4 wo = reinterpret_cast<const float4*>(wroot)[c4];
        s1 += v.x*wr.x + v.y*wr.y + v.z*wr.z + v.w*wr.w;
        s2 += v.x*wo.x + v.y*wo.y + v.z*wo.z + v.w*wo.w;
    }
#pragma unroll
    for (int o = 16; o; o >>= 1) {
        s1 += __shfl_down_sync(0xFFFFFFFFu, s1, o);
        s2 += __shfl_down_sync(0xFFFFFFFFu, s2, o);
    }
    if (lane == 0) { rrel[w] = s1; rroot[w] = s2; }
}

// ================= fused per-graph pool: smem segment-sum + RADIX-SELECT top-K =================
// One block per graph (1024 threads). Selection writes global node->newid map; edge
// remap happens in a separate full-chip kernel.
template<int NODES, int KSEL, bool WMAP>
__global__ void __launch_bounds__(1024)
pool_kernel(const float* __restrict__ rrel, const float* __restrict__ rroot,
            const float* __restrict__ brel,
            const int* __restrict__ src, const int* __restrict__ tgt,
            int* __restrict__ perm, float* __restrict__ tanhv,
            int* __restrict__ gmap)
{
    extern __shared__ char shraw[];
    float*    srrel = (float*)shraw;                  // NODES
    float*    sseg  = srrel + NODES;                  // NODES
    unsigned* skey  = (unsigned*)(sseg + NODES);      // NODES
    int*      eqL   = (int*)(skey + NODES);           // NODES
    int*      hist  = eqL + NODES;                    // 256
    int*      sCnt  = hist + 256;                     // 2 counters

    const int g   = blockIdx.x;
    const int tid = threadIdx.x;
    const int lane = tid & 31;
    const int base = g * NODES;
    const float br = brel[0];

    for (int i = tid; i < NODES; i += 1024) {
        srrel[i] = rrel[base + i];
        sseg[i] = 0.f;
    }
    __syncthreads();

    // Phase B: segment-sum over this graph's edges (smem atomics)
    for (int e = tid; e < EPG; e += 1024) {
        int s = src[g * EPG + e];
        if (s < 0) continue;
        int t = tgt[g * EPG + e];
        atomicAdd(&sseg[t - base], srrel[s - base]);
    }
    __syncthreads();

    // Phase C: monotone-mapped 32-bit keys
    for (int i = tid; i < NODES; i += 1024) {
        float sc = sseg[i] + br + rroot[base + i];
        unsigned u = __float_as_uint(sc);
        skey[i] = (u & 0x80000000u) ? ~u : (u | 0x80000000u);
    }
    __syncthreads();

    // Phase R: radix-select the KSEL-th largest key (4 x 8-bit rounds);
    // warp 0 picks the bin with a Hillis-Steele scan.
    __shared__ unsigned sPrefix;
    __shared__ int sRemain;
    if (tid == 0) { sPrefix = 0u; sRemain = KSEL; }
    __syncthreads();
#pragma unroll
    for (int round = 0; round < 4; round++) {
        const int shift = 24 - 8 * round;
        for (int b = tid; b < 256; b += 1024) hist[b] = 0;
        __syncthreads();
        unsigned prefmask = (round == 0) ? 0u : (0xFFFFFFFFu << (shift + 8));
        unsigned pref = sPrefix;
        for (int i = tid; i < NODES; i += 1024) {
            unsigned k = skey[i];
            if ((k & prefmask) == (pref & prefmask))
                atomicAdd(&hist[(k >> shift) & 255], 1);
        }
        __syncthreads();
        if (tid < 32) {
            int hi = 255 - lane * 8;
            int c[8];
            int lsum = 0;
#pragma unroll
            for (int q = 0; q < 8; q++) { c[q] = hist[hi - q]; lsum += c[q]; }
            int run = lsum;
#pragma unroll
            for (int o = 1; o < 32; o <<= 1) {
                int v = __shfl_up_sync(0xFFFFFFFFu, run, o);
                if (lane >= o) run += v;
            }
            int pre = run - lsum;
            int rem = sRemain;
            __syncwarp();
            int running = pre;
#pragma unroll
            for (int q = 0; q < 8; q++) {
                if (rem > running && rem <= running + c[q]) {
                    sRemain = rem - running;
                    sPrefix = pref | ((unsigned)(hi - q) << shift);
                }
                running += c[q];
            }
        }
        __syncthreads();
    }
    const unsigned T = sPrefix;   // exact KSEL-th largest key
    const int R = sRemain;        // how many key==T elements to select

    if (tid == 0) { sCnt[0] = 0; sCnt[1] = 0; }
    __syncthreads();

    // Phase D: selection & output (slot order irrelevant)
    for (int i = tid; i < NODES; i += 1024) {
        unsigned k = skey[i];
        if (k > T) {
            int slot = atomicAdd(&sCnt[0], 1);
            unsigned u = (k & 0x80000000u) ? (k & 0x7FFFFFFFu) : ~k;
            float sc = __uint_as_float(u);
            perm[g * KSEL + slot]  = base + i;
            tanhv[g * KSEL + slot] = tanhf(sc);
            if (WMAP) gmap[base + i] = g * KSEL + slot;
        } else if (k == T) {
            int e = atomicAdd(&sCnt[1], 1);
            eqL[e] = i;
        }
    }
    __syncthreads();
    const int neq = sCnt[1];
    // deterministic tie-break among key==T: take the R largest indices
    for (int j = tid; j < neq; j += 1024) {
        int i = eqL[j];
        int rank = 0;
        for (int l = 0; l < neq; l++) rank += (eqL[l] > i);
        if (rank < R) {
            int slot = atomicAdd(&sCnt[0], 1);
            unsigned u = (T & 0x80000000u) ? (T & 0x7FFFFFFFu) : ~T;
            float sc = __uint_as_float(u);
            perm[g * KSEL + slot]  = base + i;
            tanhv[g * KSEL + slot] = tanhf(sc);
            if (WMAP) gmap[base + i] = g * KSEL + slot;
        }
    }
}

// full-chip edge remap via global map
__global__ void remap_kernel(const int* __restrict__ src, const int* __restrict__ tgt,
                             const int* __restrict__ mapping,
                             int* __restrict__ src2, int* __restrict__ tgt2)
{
    int e = blockIdx.x * blockDim.x + threadIdx.x;
    if (e >= Ee) return;
    int s = mapping[src[e]];
    int t = mapping[tgt[e]];
    if (s < 0 || t < 0) { s = -1; t = -1; }
    src2[e] = s; tgt2[e] = t;
}

// gather + BN/ReLU + tanh-scale (float4), full-chip
__global__ void gather_kernel(const float* __restrict__ pre, const int* __restrict__ perm,
                              const float* __restrict__ scale, const float* __restrict__ shift,
                              const float* __restrict__ tv, float* __restrict__ o, int n)
{
    const int V = H1 / 4;  // 32
    int i = blockIdx.x * blockDim.x + threadIdx.x;
    if (i >= n * V) return;
    int node = i / V, off = i - node * V;
    float4 v  = reinterpret_cast<const float4*>(pre)[(size_t)perm[node] * V + off];
    float4 sc = reinterpret_cast<const float4*>(scale)[off];
    float4 sh = reinterpret_cast<const float4*>(shift)[off];
    float t = tv[node];
    v.x = fmaxf(fmaf(v.x, sc.x, sh.x), 0.f) * t;
    v.y = fmaxf(fmaf(v.y, sc.y, sh.y), 0.f) * t;
    v.z = fmaxf(fmaf(v.z, sc.z, sh.z), 0.f) * t;
    v.w = fmaxf(fmaf(v.w, sc.w, sh.w), 0.f) * t;
    reinterpret_cast<float4*>(o)[i] = v;
}

// per-graph: BN/ReLU on the fly -> pooled mean -> relu -> 256x2 linear -> softmax
__global__ void final_kernel(const float* __restrict__ pre2, const int* __restrict__ perm2,
                             const float* __restrict__ scale, const float* __restrict__ shift,
                             const float* __restrict__ tanhv2, const float* __restrict__ Wlin,
                             const float* __restrict__ blin, float* __restrict__ outp)
{
    int g = blockIdx.x, c = threadIdx.x;   // 256 threads
    __shared__ int   sp[K2];
    __shared__ float st[K2];
    for (int i = c; i < K2; i += 256) { sp[i] = perm2[g * K2 + i]; st[i] = tanhv2[g * K2 + i]; }
    __syncthreads();
    float sc = scale[c], sh = shift[c];
    float acc = 0.f;
#pragma unroll 4
    for (int r = 0; r < K2; r++)
        acc += fmaxf(fmaf(pre2[(size_t)sp[r] * H2 + c], sc, sh), 0.f) * st[r];
    float p = fmaxf(acc * (1.0f / (float)K2), 0.f);
    __shared__ float red0[256], red1[256];
    red0[c] = p * Wlin[c * 2 + 0];
    red1[c] = p * Wlin[c * 2 + 1];
    __syncthreads();
    for (int s = 128; s; s >>= 1) {
        if (c < s) { red0[c] += red0[c + s]; red1[c] += red1[c + s]; }
        __syncthreads();
    }
    if (c == 0) {
        float a = red0[0] + blin[0];
        float b = red1[0] + blin[1];
        float m = fmaxf(a, b);
        float ea = expf(a - m), eb = expf(b - m);
        float inv = 1.f / (ea + eb);
        outp[g * 2 + 0] = ea * inv;
        outp[g * 2 + 1] = eb * inv;
    }
}

// ---------------- host launch ----------------
template <typename T>
static void* symaddr(const T& s) { void* p = nullptr; cudaGetSymbolAddress(&p, s); return p; }

// pool smem: srrel + sseg + skey + eqL + hist + counters
#define POOL1_SMEM (NPG*4*4 + 256*4 + 8)   // ~33.8KB
#define POOL2_SMEM (K1*4*4 + 256*4 + 8)    // ~17.4KB
// gemm smem: W dup (BK*OD*8) + A (BK*(BM+4)*4)
#define GEMM1_SMEM (32*H1*8 + 32*(128+4)*4)   // 32768+16896 = 49664
#define GEMM2_SMEM (32*H2*8 + 32*(64+4)*4)    // 65536+8704  = 74240

extern "C" void kernel_launch(void* const* d_in, const int* in_sizes, int n_in,
                              void* d_out, int out_size)
{
    const float* x     = (const float*)d_in[0];
    const int*   ei    = (const int*)  d_in[1];
    const int*   src   = ei;
    const int*   tgt   = ei + Ee;
    const float* W1l   = (const float*)d_in[3];
    const float* b1l   = (const float*)d_in[4];
    const float* W1r   = (const float*)d_in[5];
    const float* bn1g  = (const float*)d_in[6];
    const float* bn1b  = (const float*)d_in[7];
    const float* p1Wrel  = (const float*)d_in[8];
    const float* p1brel  = (const float*)d_in[9];
    const float* p1Wroot = (const float*)d_in[10];
    const float* W2l   = (const float*)d_in[11];
    const float* b2l   = (const float*)d_in[12];
    const float* W2r   = (const float*)d_in[13];
    const float* bn2g  = (const float*)d_in[14];
    const float* bn2b  = (const float*)d_in[15];
    const float* p2Wrel  = (const float*)d_in[16];
    const float* p2brel  = (const float*)d_in[17];
    const float* p2Wroot = (const float*)d_in[18];
    const float* Wlin  = (const float*)d_in[19];
    const float* blin  = (const float*)d_in[20];
    float* out = (float*)d_out;

    float* z1    = (float*)symaddr(g_z1);
    float* agg1  = z1;
    float* cnt1  = z1 + Nn*IND;
    float* bnacc1= cnt1 + Nn;
    float* z2    = (float*)symaddr(g_z2);
    float* agg2  = z2;
    float* cnt2  = z2 + N1*H1;
    float* bnacc2= cnt2 + N1;

    float* pre1  = (float*)symaddr(g_pre1);
    int*   map1  = (int*)  symaddr(g_map1);
    int*   src2  = (int*)  symaddr(g_src2);
    int*   tgt2  = (int*)  symaddr(g_tgt2);
    float* h1new = (float*)symaddr(g_h1new);
    float* pre2  = (float*)symaddr(g_pre2);
    float* rrel  = (float*)symaddr(g_rrel);
    float* rroot = (float*)symaddr(g_rroot);
    int*   perm1 = (int*)  symaddr(g_perm1);
    float* tanh1 = (float*)symaddr(g_tanh1);
    int*   perm2 = (int*)  symaddr(g_perm2);
    float* tanh2 = (float*)symaddr(g_tanh2);
    float* scale = (float*)symaddr(g_scale);
    float* shift = (float*)symaddr(g_shift);
    int*   ctr1  = (int*)  symaddr(g_ctr1);
    int*   ctr2  = (int*)  symaddr(g_ctr2);

    cudaFuncSetAttribute((const void*)gemm_dual6<IND, H1, 128, 16>,
                         cudaFuncAttributeMaxDynamicSharedMemorySize, GEMM1_SMEM);
    cudaFuncSetAttribute((const void*)gemm_dual6<H1, H2, 64, 32>,
                         cudaFuncAttributeMaxDynamicSharedMemorySize, GEMM2_SMEM);
    cudaFuncSetAttribute((const void*)pool_kernel<NPG, K1, true>,
                         cudaFuncAttributeMaxDynamicSharedMemorySize, POOL1_SMEM);
    cudaFuncSetAttribute((const void*)pool_kernel<K1, K2, false>,
                         cudaFuncAttributeMaxDynamicSharedMemorySize, POOL2_SMEM);

    // ---- zero-fill (all up front) ----
    cudaMemsetAsync(z1, 0, sizeof(float)*Z1_FLOATS);
    cudaMemsetAsync(z2, 0, sizeof(float)*Z2_FLOATS);
    cudaMemsetAsync(map1, 0xFF, sizeof(int)*Nn);   // -1

    // ---- stage 1 ----
    agg_kernel<IND><<<AGG_BLOCKS, 256>>>(src, tgt, x, agg1, cnt1, Ee);
    gemm_dual6<IND, H1, 128, 16><<<Nn/128, 256, GEMM1_SMEM>>>(
        agg1, cnt1, x, W1l, W1r, b1l, pre1,
        bnacc1, ctr1, bn1g, bn1b, scale, shift, 1.f/(float)Nn);
    bnad_kernel<H1><<<Nn/8, 256>>>(pre1, scale, shift, p1Wrel, p1Wroot, rrel, rroot, Nn);
    pool_kernel<NPG, K1, true><<<Bg, 1024, POOL1_SMEM>>>(
        rrel, rroot, p1brel, src, tgt, perm1, tanh1, map1);
    remap_kernel<<<Ee/256, 256>>>(src, tgt, map1, src2, tgt2);
    gather_kernel<<<(N1*(H1/4))/256, 256>>>(pre1, perm1, scale, shift, tanh1, h1new, N1);

    // ---- stage 2 ----
    agg_kernel<H1><<<AGG_BLOCKS, 256>>>(src2, tgt2, h1new, agg2, cnt2, Ee);
    gemm_dual6<H1, H2, 64, 32><<<N1/64, 256, GEMM2_SMEM>>>(
        agg2, cnt2, h1new, W2l, W2r, b2l, pre2,
        bnacc2, ctr2, bn2g, bn2b, scale, shift, 1.f/(float)N1);
    bnad_kernel<H2><<<N1/8, 256>>>(pre2, scale, shift, p2Wrel, p2Wroot, rrel, rroot, N1);
    pool_kernel<K1, K2, false><<<Bg, 1024, POOL2_SMEM>>>(
        rrel, rroot, p2brel, src2, tgt2, perm2, tanh2, nullptr);

    // ---- readout ----
    final_kernel<<<Bg, 256>>>(pre2, perm2, scale, shift, tanh2, Wlin, blin, out);

    (void)in_sizes; (void)n_in; (void)out_size;
}

// round 14
// speedup vs baseline: 1.7834x; 1.7834x over previous
#include <cuda_runtime.h>
#include <math.h>

// ---------------- problem constants ----------------
#define Bg   32
#define NPG  2048
#define Nn   (Bg*NPG)        // 65536
#define Ee   (Nn*8)          // 524288
#define EPG  (Ee/Bg)         // 16384 edges per graph (contiguous per graph!)
#define IND  64
#define H1   128
#define H2   256
#define K1   1024
#define K2   512
#define N1   (Bg*K1)         // 32768
#define N2   (Bg*K2)         // 16384

#define AGG_BLOCKS 2368      // 16 CTAs/SM x 148 SMs, grid-stride

// ---------------- scratch (device globals; no allocs) ----------------
#define Z1_FLOATS (Nn*IND + Nn + 2*H1)
__device__ float g_z1[Z1_FLOATS];    // [agg1 | cnt1 | bnacc1]
#define Z2_FLOATS (N1*H1 + N1 + 2*H2)
__device__ float g_z2[Z2_FLOATS];    // [agg2 | cnt2 | bnacc2]

__device__ float g_pre1 [Nn*H1];
__device__ int   g_map1 [Nn];
__device__ int   g_src2 [Ee];
__device__ int   g_tgt2 [Ee];
__device__ float g_h1new[N1*H1];
__device__ float g_pre2 [N1*H2];
__device__ float g_rrel [Nn];
__device__ float g_rroot[Nn];
__device__ int   g_perm1[N1];
__device__ float g_tanh1[N1];
__device__ int   g_perm2[N2];
__device__ float g_tanh2[N2];
__device__ float g_scale[H2];
__device__ float g_shift[H2];
__device__ int   g_ctr1 = 0;
__device__ int   g_ctr2 = 0;

// ---------------- helpers ----------------
__device__ __forceinline__ unsigned long long pk2(float lo, float hi) {
    unsigned long long r;
    asm("mov.b64 %0, {%1,%2};" : "=l"(r) : "f"(lo), "f"(hi));
    return r;
}
__device__ __forceinline__ void upk2(unsigned long long v, float& lo, float& hi) {
    asm("mov.b64 {%0,%1}, %2;" : "=f"(lo), "=f"(hi) : "l"(v));
}
__device__ __forceinline__ void ffma2(unsigned long long& d, unsigned long long a, unsigned long long b) {
    asm("fma.rn.f32x2 %0, %1, %2, %0;" : "+l"(d) : "l"(a), "l"(b));
}
__device__ __forceinline__ void cp_async16(float* smem, const float* gmem) {
    unsigned saddr = (unsigned)__cvta_generic_to_shared(smem);
    asm volatile("cp.async.cg.shared.global [%0], [%1], 16;" :: "r"(saddr), "l"(gmem) : "memory");
}

// ---------------- kernels ----------------

// grid-stride mean aggregation: one (edge, float4) work item per loop step
template<int D>
__global__ void agg_kernel(const int* __restrict__ src, const int* __restrict__ tgt,
                           const float* __restrict__ xin, float* __restrict__ aggo,
                           float* __restrict__ cnt, int nedges)
{
    const int V = D / 4;
    const int total = nedges * V;
    const int stride = gridDim.x * blockDim.x;
    for (int i = blockIdx.x * blockDim.x + threadIdx.x; i < total; i += stride) {
        int e  = i / V;
        int f4 = i - e * V;
        int s = src[e];
        if (s < 0) continue;
        int t = tgt[e];
        float4 v = reinterpret_cast<const float4*>(xin)[(size_t)s * V + f4];
        asm volatile("red.global.add.v4.f32 [%0], {%1,%2,%3,%4};"
                     :: "l"(&aggo[(size_t)t * D + f4 * 4]),
                        "f"(v.x), "f"(v.y), "f"(v.z), "f"(v.w) : "memory");
        if (f4 == 0) atomicAdd(&cnt[t], 1.0f);
    }
}

// pre[n,OD] = (agg[n]/max(cnt,1)) @ Wl + xin @ Wr + bias   (K concat, FFMA2)
// Pipelined staging: W via cp.async, A via prefetched float4 LDG (one kt ahead).
// Epilogue: per-column sum/sumsq into bnacc; last block computes scale/shift.
template<int KD, int OD, int BM, int CG>
__global__ void __launch_bounds__(256)
gemm_dual5(const float* __restrict__ agg, const float* __restrict__ cnt,
           const float* __restrict__ xin,
           const float* __restrict__ Wl, const float* __restrict__ Wr,
           const float* __restrict__ bias, float* __restrict__ outp,
           float* __restrict__ bnacc, int* __restrict__ ctr,
           const float* __restrict__ bng, const float* __restrict__ bnb,
           float* __restrict__ scale, float* __restrict__ shift,
           float invn)
{
    const int TN = 8, BK = 32, ASTR = BM + 4;
    const int NTY = 256 / CG;
    const int NK  = 2 * KD / BK;
    const int ALD = BM * BK / (4 * 256);
    const int WLD = BK * OD / (4 * 256);
    extern __shared__ float sh[];
    float* sW = sh;
    float* sA = sh + BK * OD;

    int tid = threadIdx.x;
    int tx  = tid % CG;
    int ty  = tid / CG;
    int row0 = blockIdx.x * BM;

    unsigned long long acc[4][TN];
#pragma unroll
    for (int r = 0; r < 4; r++)
#pragma unroll
        for (int j = 0; j < TN; j++) acc[r][j] = 0ull;

    float4 areg[ALD];
    float  ainv[ALD];

#pragma unroll
    for (int j = 0; j < ALD; j++) {
        int idx = tid + j * 256;
        int m = idx >> 3, kq = idx & 7;
        int row = row0 + m;
        int kg = 4 * kq;
        if (kg < KD) {
            areg[j] = *reinterpret_cast<const float4*>(&agg[(size_t)row * KD + kg]);
            ainv[j] = 1.f / fmaxf(cnt[row], 1.f);
        } else {
            areg[j] = *reinterpret_cast<const float4*>(&xin[(size_t)row * KD + (kg - KD)]);
            ainv[j] = 1.f;
        }
    }

    for (int kti = 0; kti < NK; kti++) {
        int kt = kti * BK;
        __syncthreads();

#pragma unroll
        for (int j = 0; j < WLD; j++) {
            int idx = tid + j * 256;
            int k = idx / (OD / 4), cq = idx % (OD / 4);
            int kg = kt + k;
            const float* gsrc = (kg < KD) ? &Wl[(size_t)kg * OD + 4 * cq]
                                          : &Wr[(size_t)(kg - KD) * OD + 4 * cq];
            cp_async16(&sW[k * OD + 4 * cq], gsrc);
        }
        asm volatile("cp.async.commit_group;" ::: "memory");

#pragma unroll
        for (int j = 0; j < ALD; j++) {
            int idx = tid + j * 256;
            int m = idx >> 3, kq = idx & 7;
            float iv = ainv[j];
            sA[(4*kq+0) * ASTR + m] = areg[j].x * iv;
            sA[(4*kq+1) * ASTR + m] = areg[j].y * iv;
            sA[(4*kq+2) * ASTR + m] = areg[j].z * iv;
            sA[(4*kq+3) * ASTR + m] = areg[j].w * iv;
        }

        if (kti + 1 < NK) {
            int ktn = kt + BK;
#pragma unroll
            for (int j = 0; j < ALD; j++) {
                int idx = tid + j * 256;
                int m = idx >> 3, kq = idx & 7;
                int row = row0 + m;
                int kg = ktn + 4 * kq;
                if (kg < KD) {
                    areg[j] = *reinterpret_cast<const float4*>(&agg[(size_t)row * KD + kg]);
                    ainv[j] = 1.f / fmaxf(cnt[row], 1.f);
                } else {
                    areg[j] = *reinterpret_cast<const float4*>(&xin[(size_t)row * KD + (kg - KD)]);
                    ainv[j] = 1.f;
                }
            }
        }

        asm volatile("cp.async.wait_group 0;" ::: "memory");
        __syncthreads();

#pragma unroll
        for (int k = 0; k < BK; k++) {
            const float4 a0 = *reinterpret_cast<const float4*>(&sA[k * ASTR + ty * 8]);
            const float4 a1 = *reinterpret_cast<const float4*>(&sA[k * ASTR + ty * 8 + 4]);
            unsigned long long ap[4] = { pk2(a0.x, a0.y), pk2(a0.z, a0.w),
                                         pk2(a1.x, a1.y), pk2(a1.z, a1.w) };
#pragma unroll
            for (int jj = 0; jj < TN / 4; jj++) {
                float4 w4 = *reinterpret_cast<const float4*>(&sW[k * OD + tx * TN + jj * 4]);
                unsigned long long w0 = pk2(w4.x, w4.x), w1 = pk2(w4.y, w4.y);
                unsigned long long w2 = pk2(w4.z, w4.z), w3 = pk2(w4.w, w4.w);
#pragma unroll
                for (int r = 0; r < 4; r++) {
                    ffma2(acc[r][jj*4+0], ap[r], w0);
                    ffma2(acc[r][jj*4+1], ap[r], w1);
                    ffma2(acc[r][jj*4+2], ap[r], w2);
                    ffma2(acc[r][jj*4+3], ap[r], w3);
                }
            }
        }
    }

    float cs[TN], cs2[TN];
#pragma unroll
    for (int j = 0; j < TN; j++) { cs[j] = 0.f; cs2[j] = 0.f; }
    float bb[TN];
#pragma unroll
    for (int jj = 0; jj < TN / 4; jj++) {
        float4 b4 = *reinterpret_cast<const float4*>(&bias[tx * TN + jj * 4]);
        bb[jj*4+0]=b4.x; bb[jj*4+1]=b4.y; bb[jj*4+2]=b4.z; bb[jj*4+3]=b4.w;
    }
#pragma unroll
    for (int r = 0; r < 4; r++) {
        float lo[TN], hi[TN];
#pragma unroll
        for (int j = 0; j < TN; j++) {
            upk2(acc[r][j], lo[j], hi[j]);
            lo[j] += bb[j]; hi[j] += bb[j];
            cs[j]  += lo[j] + hi[j];
            cs2[j] += lo[j]*lo[j] + hi[j]*hi[j];
        }
        int row_lo = row0 + ty * 8 + 2 * r;
#pragma unroll
        for (int jj = 0; jj < TN / 4; jj++) {
            int c = tx * TN + jj * 4;
            *reinterpret_cast<float4*>(&outp[(size_t)row_lo * OD + c]) =
                make_float4(lo[jj*4], lo[jj*4+1], lo[jj*4+2], lo[jj*4+3]);
            *reinterpret_cast<float4*>(&outp[(size_t)(row_lo+1) * OD + c]) =
                make_float4(hi[jj*4], hi[jj*4+1], hi[jj*4+2], hi[jj*4+3]);
        }
    }

    __syncthreads();
    float* sRed = sh;
#pragma unroll
    for (int j = 0; j < TN; j++) sRed[ty * OD + tx * TN + j] = cs[j];
    __syncthreads();
    for (int c = tid; c < OD; c += 256) {
        float t = 0.f;
#pragma unroll
        for (int i = 0; i < NTY; i++) t += sRed[i * OD + c];
        atomicAdd(&bnacc[c], t);
    }
    __syncthreads();
#pragma unroll
    for (int j = 0; j < TN; j++) sRed[ty * OD + tx * TN + j] = cs2[j];
    __syncthreads();
    for (int c = tid; c < OD; c += 256) {
        float t = 0.f;
#pragma unroll
        for (int i = 0; i < NTY; i++) t += sRed[i * OD + c];
        atomicAdd(&bnacc[OD + c], t);
    }

    __shared__ int sDone;
    __threadfence();
    if (tid == 0) {
        int old = atomicAdd(ctr, 1);
        sDone = (old == (int)gridDim.x - 1);
    }
    __syncthreads();
    if (sDone) {
        if (tid < OD) {
            float s  = __ldcg(&bnacc[tid]);
            float s2 = __ldcg(&bnacc[OD + tid]);
            float m   = s * invn;
            float var = s2 * invn - m * m;
            float sc  = rsqrtf(var + 1e-5f) * bng[tid];
            scale[tid] = sc;
            shift[tid] = bnb[tid] - m * sc;
        }
        if (tid == 0) *ctr = 0;
    }
}

// fused: BN apply (registers only) + ReLU + two score dot products. One warp per row.
template<int D>
__global__ void bnad_kernel(const float* __restrict__ pre, const float* __restrict__ scale,
                            const float* __restrict__ shift,
                            const float* __restrict__ wrel, const float* __restrict__ wroot,
                            float* __restrict__ rrel, float* __restrict__ rroot, int nrows)
{
    int w = (blockIdx.x * blockDim.x + threadIdx.x) >> 5;
    int lane = threadIdx.x & 31;
    if (w >= nrows) return;
    const int V = D / 128;
    float s1 = 0.f, s2 = 0.f;
    const float4* rowp = reinterpret_cast<const float4*>(pre + (size_t)w * D);
#pragma unroll
    for (int q = 0; q < V; q++) {
        int c4 = lane + q * 32;
        float4 v  = rowp[c4];
        float4 sc = reinterpret_cast<const float4*>(scale)[c4];
        float4 sh = reinterpret_cast<const float4*>(shift)[c4];
        v.x = fmaxf(fmaf(v.x, sc.x, sh.x), 0.f);
        v.y = fmaxf(fmaf(v.y, sc.y, sh.y), 0.f);
        v.z = fmaxf(fmaf(v.z, sc.z, sh.z), 0.f);
        v.w = fmaxf(fmaf(v.w, sc.w, sh.w), 0.f);
        float4 wr = reinterpret_cast<const float4*>(wrel)[c4];
        float4 wo = reinterpret_cast<const float4*>(wroot)[c4];
        s1 += v.x*wr.x + v.y*wr.y + v.z*wr.z + v.w*wr.w;
        s2 += v.x*wo.x + v.y*wo.y + v.z*wo.z + v.w*wo.w;
    }
#pragma unroll
    for (int o = 16; o; o >>= 1) {
        s1 += __shfl_down_sync(0xFFFFFFFFu, s1, o);
        s2 += __shfl_down_sync(0xFFFFFFFFu, s2, o);
    }
    if (lane == 0) { rrel[w] = s1; rroot[w] = s2; }
}

// ================= fused per-graph pool: smem segment-sum + RADIX-SELECT top-K =================
// One block per graph (1024 threads). Selection writes global node->newid map; edge
// remap happens in a separate full-chip kernel.
template<int NODES, int KSEL, bool WMAP>
__global__ void __launch_bounds__(1024)
pool_kernel(const float* __restrict__ rrel, const float* __restrict__ rroot,
            const float* __restrict__ brel,
            const int* __restrict__ src, const int* __restrict__ tgt,
            int* __restrict__ perm, float* __restrict__ tanhv,
            int* __restrict__ gmap)
{
    extern __shared__ char shraw[];
    float*    srrel = (float*)shraw;                  // NODES
    float*    sseg  = srrel + NODES;                  // NODES
    unsigned* skey  = (unsigned*)(sseg + NODES);      // NODES
    int*      eqL   = (int*)(skey + NODES);           // NODES
    int*      hist  = eqL + NODES;                    // 256
    int*      sCnt  = hist + 256;                     // 2 counters

    const int g   = blockIdx.x;
    const int tid = threadIdx.x;
    const int lane = tid & 31;
    const int base = g * NODES;
    const float br = brel[0];

    for (int i = tid; i < NODES; i += 1024) {
        srrel[i] = rrel[base + i];
        sseg[i] = 0.f;
    }
    __syncthreads();

    // Phase B: segment-sum over this graph's edges (smem atomics)
    for (int e = tid; e < EPG; e += 1024) {
        int s = src[g * EPG + e];
        if (s < 0) continue;
        int t = tgt[g * EPG + e];
        atomicAdd(&sseg[t - base], srrel[s - base]);
    }
    __syncthreads();

    // Phase C: monotone-mapped 32-bit keys
    for (int i = tid; i < NODES; i += 1024) {
        float sc = sseg[i] + br + rroot[base + i];
        unsigned u = __float_as_uint(sc);
        skey[i] = (u & 0x80000000u) ? ~u : (u | 0x80000000u);
    }
    __syncthreads();

    // Phase R: radix-select the KSEL-th largest key (4 x 8-bit rounds);
    // warp 0 picks the bin with a Hillis-Steele scan.
    __shared__ unsigned sPrefix;
    __shared__ int sRemain;
    if (tid == 0) { sPrefix = 0u; sRemain = KSEL; }
    __syncthreads();
#pragma unroll
    for (int round = 0; round < 4; round++) {
        const int shift = 24 - 8 * round;
        for (int b = tid; b < 256; b += 1024) hist[b] = 0;
        __syncthreads();
        unsigned prefmask = (round == 0) ? 0u : (0xFFFFFFFFu << (shift + 8));
        unsigned pref = sPrefix;
        for (int i = tid; i < NODES; i += 1024) {
            unsigned k = skey[i];
            if ((k & prefmask) == (pref & prefmask))
                atomicAdd(&hist[(k >> shift) & 255], 1);
        }
        __syncthreads();
        if (tid < 32) {
            int hi = 255 - lane * 8;
            int c[8];
            int lsum = 0;
#pragma unroll
            for (int q = 0; q < 8; q++) { c[q] = hist[hi - q]; lsum += c[q]; }
            int run = lsum;
#pragma unroll
            for (int o = 1; o < 32; o <<= 1) {
                int v = __shfl_up_sync(0xFFFFFFFFu, run, o);
                if (lane >= o) run += v;
            }
            int pre = run - lsum;
            int rem = sRemain;
            __syncwarp();
            int running = pre;
#pragma unroll
            for (int q = 0; q < 8; q++) {
                if (rem > running && rem <= running + c[q]) {
                    sRemain = rem - running;
                    sPrefix = pref | ((unsigned)(hi - q) << shift);
                }
                running += c[q];
            }
        }
        __syncthreads();
    }
    const unsigned T = sPrefix;   // exact KSEL-th largest key
    const int R = sRemain;        // how many key==T elements to select

    if (tid == 0) { sCnt[0] = 0; sCnt[1] = 0; }
    __syncthreads();

    // Phase D: selection & output (slot order irrelevant)
    for (int i = tid; i < NODES; i += 1024) {
        unsigned k = skey[i];
        if (k > T) {
            int slot = atomicAdd(&sCnt[0], 1);
            unsigned u = (k & 0x80000000u) ? (k & 0x7FFFFFFFu) : ~k;
            float sc = __uint_as_float(u);
            perm[g * KSEL + slot]  = base + i;
            tanhv[g * KSEL + slot] = tanhf(sc);
            if (WMAP) gmap[base + i] = g * KSEL + slot;
        } else if (k == T) {
            int e = atomicAdd(&sCnt[1], 1);
            eqL[e] = i;
        }
    }
    __syncthreads();
    const int neq = sCnt[1];
    // deterministic tie-break among key==T: take the R largest indices
    for (int j = tid; j < neq; j += 1024) {
        int i = eqL[j];
        int rank = 0;
        for (int l = 0; l < neq; l++) rank += (eqL[l] > i);
        if (rank < R) {
            int slot = atomicAdd(&sCnt[0], 1);
            unsigned u = (T & 0x80000000u) ? (T & 0x7FFFFFFFu) : ~T;
            float sc = __uint_as_float(u);
            perm[g * KSEL + slot]  = base + i;
            tanhv[g * KSEL + slot] = tanhf(sc);
            if (WMAP) gmap[base + i] = g * KSEL + slot;
        }
    }
}

// full-chip edge remap via global map
__global__ void remap_kernel(const int* __restrict__ src, const int* __restrict__ tgt,
                             const int* __restrict__ mapping,
                             int* __restrict__ src2, int* __restrict__ tgt2)
{
    int e = blockIdx.x * blockDim.x + threadIdx.x;
    if (e >= Ee) return;
    int s = mapping[src[e]];
    int t = mapping[tgt[e]];
    if (s < 0 || t < 0) { s = -1; t = -1; }
    src2[e] = s; tgt2[e] = t;
}

// gather + BN/ReLU + tanh-scale (float4), full-chip
__global__ void gather_kernel(const float* __restrict__ pre, const int* __restrict__ perm,
                              const float* __restrict__ scale, const float* __restrict__ shift,
                              const float* __restrict__ tv, float* __restrict__ o, int n)
{
    const int V = H1 / 4;  // 32
    int i = blockIdx.x * blockDim.x + threadIdx.x;
    if (i >= n * V) return;
    int node = i / V, off = i - node * V;
    float4 v  = reinterpret_cast<const float4*>(pre)[(size_t)perm[node] * V + off];
    float4 sc = reinterpret_cast<const float4*>(scale)[off];
    float4 sh = reinterpret_cast<const float4*>(shift)[off];
    float t = tv[node];
    v.x = fmaxf(fmaf(v.x, sc.x, sh.x), 0.f) * t;
    v.y = fmaxf(fmaf(v.y, sc.y, sh.y), 0.f) * t;
    v.z = fmaxf(fmaf(v.z, sc.z, sh.z), 0.f) * t;
    v.w = fmaxf(fmaf(v.w, sc.w, sh.w), 0.f) * t;
    reinterpret_cast<float4*>(o)[i] = v;
}

// per-graph: BN/ReLU on the fly -> pooled mean -> relu -> 256x2 linear -> softmax
__global__ void final_kernel(const float* __restrict__ pre2, const int* __restrict__ perm2,
                             const float* __restrict__ scale, const float* __restrict__ shift,
                             const float* __restrict__ tanhv2, const float* __restrict__ Wlin,
                             const float* __restrict__ blin, float* __restrict__ outp)
{
    int g = blockIdx.x, c = threadIdx.x;   // 256 threads
    __shared__ int   sp[K2];
    __shared__ float st[K2];
    for (int i = c; i < K2; i += 256) { sp[i] = perm2[g * K2 + i]; st[i] = tanhv2[g * K2 + i]; }
    __syncthreads();
    float sc = scale[c], sh = shift[c];
    float acc = 0.f;
#pragma unroll 4
    for (int r = 0; r < K2; r++)
        acc += fmaxf(fmaf(pre2[(size_t)sp[r] * H2 + c], sc, sh), 0.f) * st[r];
    float p = fmaxf(acc * (1.0f / (float)K2), 0.f);
    __shared__ float red0[256], red1[256];
    red0[c] = p * Wlin[c * 2 + 0];
    red1[c] = p * Wlin[c * 2 + 1];
    __syncthreads();
    for (int s = 128; s; s >>= 1) {
        if (c < s) { red0[c] += red0[c + s]; red1[c] += red1[c + s]; }
        __syncthreads();
    }
    if (c == 0) {
        float a = red0[0] + blin[0];
        float b = red1[0] + blin[1];
        float m = fmaxf(a, b);
        float ea = expf(a - m), eb = expf(b - m);
        float inv = 1.f / (ea + eb);
        outp[g * 2 + 0] = ea * inv;
        outp[g * 2 + 1] = eb * inv;
    }
}

// ---------------- host launch ----------------
template <typename T>
static void* symaddr(const T& s) { void* p = nullptr; cudaGetSymbolAddress(&p, s); return p; }

// pool smem: srrel + sseg + skey + eqL + hist + counters
#define POOL1_SMEM (NPG*4*4 + 256*4 + 8)   // ~33.8KB
#define POOL2_SMEM (K1*4*4 + 256*4 + 8)    // ~17.4KB

extern "C" void kernel_launch(void* const* d_in, const int* in_sizes, int n_in,
                              void* d_out, int out_size)
{
    const float* x     = (const float*)d_in[0];
    const int*   ei    = (const int*)  d_in[1];
    const int*   src   = ei;
    const int*   tgt   = ei + Ee;
    const float* W1l   = (const float*)d_in[3];
    const float* b1l   = (const float*)d_in[4];
    const float* W1r   = (const float*)d_in[5];
    const float* bn1g  = (const float*)d_in[6];
    const float* bn1b  = (const float*)d_in[7];
    const float* p1Wrel  = (const float*)d_in[8];
    const float* p1brel  = (const float*)d_in[9];
    const float* p1Wroot = (const float*)d_in[10];
    const float* W2l   = (const float*)d_in[11];
    const float* b2l   = (const float*)d_in[12];
    const float* W2r   = (const float*)d_in[13];
    const float* bn2g  = (const float*)d_in[14];
    const float* bn2b  = (const float*)d_in[15];
    const float* p2Wrel  = (const float*)d_in[16];
    const float* p2brel  = (const float*)d_in[17];
    const float* p2Wroot = (const float*)d_in[18];
    const float* Wlin  = (const float*)d_in[19];
    const float* blin  = (const float*)d_in[20];
    float* out = (float*)d_out;

    float* z1    = (float*)symaddr(g_z1);
    float* agg1  = z1;
    float* cnt1  = z1 + Nn*IND;
    float* bnacc1= cnt1 + Nn;
    float* z2    = (float*)symaddr(g_z2);
    float* agg2  = z2;
    float* cnt2  = z2 + N1*H1;
    float* bnacc2= cnt2 + N1;

    float* pre1  = (float*)symaddr(g_pre1);
    int*   map1  = (int*)  symaddr(g_map1);
    int*   src2  = (int*)  symaddr(g_src2);
    int*   tgt2  = (int*)  symaddr(g_tgt2);
    float* h1new = (float*)symaddr(g_h1new);
    float* pre2  = (float*)symaddr(g_pre2);
    float* rrel  = (float*)symaddr(g_rrel);
    float* rroot = (float*)symaddr(g_rroot);
    int*   perm1 = (int*)  symaddr(g_perm1);
    float* tanh1 = (float*)symaddr(g_tanh1);
    int*   perm2 = (int*)  symaddr(g_perm2);
    float* tanh2 = (float*)symaddr(g_tanh2);
    float* scale = (float*)symaddr(g_scale);
    float* shift = (float*)symaddr(g_shift);
    int*   ctr1  = (int*)  symaddr(g_ctr1);
    int*   ctr2  = (int*)  symaddr(g_ctr2);

    cudaFuncSetAttribute((const void*)gemm_dual5<IND, H1, 128, 16>,
                         cudaFuncAttributeMaxDynamicSharedMemorySize, 33280);
    cudaFuncSetAttribute((const void*)gemm_dual5<H1, H2, 64, 32>,
                         cudaFuncAttributeMaxDynamicSharedMemorySize, 41472);
    cudaFuncSetAttribute((const void*)pool_kernel<NPG, K1, true>,
                         cudaFuncAttributeMaxDynamicSharedMemorySize, POOL1_SMEM);
    cudaFuncSetAttribute((const void*)pool_kernel<K1, K2, false>,
                         cudaFuncAttributeMaxDynamicSharedMemorySize, POOL2_SMEM);

    // ---- zero-fill (all up front) ----
    cudaMemsetAsync(z1, 0, sizeof(float)*Z1_FLOATS);
    cudaMemsetAsync(z2, 0, sizeof(float)*Z2_FLOATS);
    cudaMemsetAsync(map1, 0xFF, sizeof(int)*Nn);   // -1

    // ---- stage 1 ----
    agg_kernel<IND><<<AGG_BLOCKS, 256>>>(src, tgt, x, agg1, cnt1, Ee);
    gemm_dual5<IND, H1, 128, 16><<<Nn/128, 256, 33280>>>(
        agg1, cnt1, x, W1l, W1r, b1l, pre1,
        bnacc1, ctr1, bn1g, bn1b, scale, shift, 1.f/(float)Nn);
    bnad_kernel<H1><<<Nn/8, 256>>>(pre1, scale, shift, p1Wrel, p1Wroot, rrel, rroot, Nn);
    pool_kernel<NPG, K1, true><<<Bg, 1024, POOL1_SMEM>>>(
        rrel, rroot, p1brel, src, tgt, perm1, tanh1, map1);
    remap_kernel<<<Ee/256, 256>>>(src, tgt, map1, src2, tgt2);
    gather_kernel<<<(N1*(H1/4))/256, 256>>>(pre1, perm1, scale, shift, tanh1, h1new, N1);

    // ---- stage 2 ----
    agg_kernel<H1><<<AGG_BLOCKS, 256>>>(src2, tgt2, h1new, agg2, cnt2, Ee);
    gemm_dual5<H1, H2, 64, 32><<<N1/64, 256, 41472>>>(
        agg2, cnt2, h1new, W2l, W2r, b2l, pre2,
        bnacc2, ctr2, bn2g, bn2b, scale, shift, 1.f/(float)N1);
    bnad_kernel<H2><<<N1/8, 256>>>(pre2, scale, shift, p2Wrel, p2Wroot, rrel, rroot, N1);
    pool_kernel<K1, K2, false><<<Bg, 1024, POOL2_SMEM>>>(
        rrel, rroot, p2brel, src2, tgt2, perm2, tanh2, nullptr);

    // ---- readout ----
    final_kernel<<<Bg, 256>>>(pre2, perm2, scale, shift, tanh2, Wlin, blin, out);

    (void)in_sizes; (void)n_in; (void)out_size;
}

// round 15
// speedup vs baseline: 2.0634x; 1.1570x over previous
#include <cuda_runtime.h>
#include <math.h>

// ---------------- problem constants ----------------
#define Bg   32
#define NPG  2048
#define Nn   (Bg*NPG)        // 65536
#define Ee   (Nn*8)          // 524288
#define EPG  (Ee/Bg)         // 16384 edges per graph (contiguous per graph!)
#define IND  64
#define H1   128
#define H2   256
#define K1   1024
#define K2   512
#define N1   (Bg*K1)         // 32768
#define N2   (Bg*K2)         // 16384

#define AGG_BLOCKS 2368      // 16 CTAs/SM x 148 SMs, grid-stride

// ---------------- scratch (device globals; no allocs) ----------------
#define Z1_FLOATS (Nn*IND + Nn + 2*H1)
__device__ float g_z1[Z1_FLOATS];    // [agg1 | cnt1 | bnacc1]
#define Z2_FLOATS (N1*H1 + N1 + 2*H2 + Bg*H2)
__device__ float g_z2[Z2_FLOATS];    // [agg2 | cnt2 | bnacc2 | gacc]

__device__ float g_pre1 [Nn*H1];
__device__ int   g_map1 [Nn];
__device__ int   g_src2 [Ee];
__device__ int   g_tgt2 [Ee];
__device__ float g_h1new[N1*H1];
__device__ float g_pre2 [N1*H2];
__device__ float g_rrel [Nn];
__device__ float g_rroot[Nn];
__device__ int   g_perm1[N1];
__device__ float g_tanh1[N1];
__device__ int   g_perm2[N2];
__device__ float g_tanh2[N2];
__device__ float g_scale[H2];
__device__ float g_shift[H2];
__device__ int   g_ctr1 = 0;
__device__ int   g_ctr2 = 0;

// ---------------- helpers ----------------
__device__ __forceinline__ unsigned long long pk2(float lo, float hi) {
    unsigned long long r;
    asm("mov.b64 %0, {%1,%2};" : "=l"(r) : "f"(lo), "f"(hi));
    return r;
}
__device__ __forceinline__ void upk2(unsigned long long v, float& lo, float& hi) {
    asm("mov.b64 {%0,%1}, %2;" : "=f"(lo), "=f"(hi) : "l"(v));
}
__device__ __forceinline__ void ffma2(unsigned long long& d, unsigned long long a, unsigned long long b) {
    asm("fma.rn.f32x2 %0, %1, %2, %0;" : "+l"(d) : "l"(a), "l"(b));
}
__device__ __forceinline__ void cp_async16(float* smem, const float* gmem) {
    unsigned saddr = (unsigned)__cvta_generic_to_shared(smem);
    asm volatile("cp.async.cg.shared.global [%0], [%1], 16;" :: "r"(saddr), "l"(gmem) : "memory");
}

// ---------------- kernels ----------------

// grid-stride mean aggregation: one (edge, float4) work item per loop step
template<int D>
__global__ void agg_kernel(const int* __restrict__ src, const int* __restrict__ tgt,
                           const float* __restrict__ xin, float* __restrict__ aggo,
                           float* __restrict__ cnt, int nedges)
{
    const int V = D / 4;
    const int total = nedges * V;
    const int stride = gridDim.x * blockDim.x;
    for (int i = blockIdx.x * blockDim.x + threadIdx.x; i < total; i += stride) {
        int e  = i / V;
        int f4 = i - e * V;
        int s = src[e];
        if (s < 0) continue;
        int t = tgt[e];
        float4 v = reinterpret_cast<const float4*>(xin)[(size_t)s * V + f4];
        asm volatile("red.global.add.v4.f32 [%0], {%1,%2,%3,%4};"
                     :: "l"(&aggo[(size_t)t * D + f4 * 4]),
                        "f"(v.x), "f"(v.y), "f"(v.z), "f"(v.w) : "memory");
        if (f4 == 0) atomicAdd(&cnt[t], 1.0f);
    }
}

// pre[n,OD] = (agg[n]/max(cnt,1)) @ Wl + xin @ Wr + bias   (K concat, FFMA2)
// A read as packed ulonglong2 row-pairs (zero A-pack movs). W float4 + broadcast movs
// (duplicated-W variant regressed: doubles LDS bytes). W via cp.async; A prefetched.
// Epilogue: per-column sum/sumsq into bnacc; last block computes scale/shift.
template<int KD, int OD, int BM, int CG>
__global__ void __launch_bounds__(256)
gemm_dual7(const float* __restrict__ agg, const float* __restrict__ cnt,
           const float* __restrict__ xin,
           const float* __restrict__ Wl, const float* __restrict__ Wr,
           const float* __restrict__ bias, float* __restrict__ outp,
           float* __restrict__ bnacc, int* __restrict__ ctr,
           const float* __restrict__ bng, const float* __restrict__ bnb,
           float* __restrict__ scale, float* __restrict__ shift,
           float invn)
{
    const int TN = 8, BK = 32, ASTR = BM + 4;
    const int NTY = 256 / CG;
    const int NK  = 2 * KD / BK;
    const int ALD = BM * BK / (4 * 256);
    const int WLD = BK * OD / (4 * 256);
    extern __shared__ float sh[];
    float* sW = sh;
    float* sA = sh + BK * OD;

    int tid = threadIdx.x;
    int tx  = tid % CG;
    int ty  = tid / CG;
    int row0 = blockIdx.x * BM;

    unsigned long long acc[4][TN];
#pragma unroll
    for (int r = 0; r < 4; r++)
#pragma unroll
        for (int j = 0; j < TN; j++) acc[r][j] = 0ull;

    float4 areg[ALD];
    float  ainv[ALD];

#pragma unroll
    for (int j = 0; j < ALD; j++) {
        int idx = tid + j * 256;
        int m = idx >> 3, kq = idx & 7;
        int row = row0 + m;
        int kg = 4 * kq;
        if (kg < KD) {
            areg[j] = *reinterpret_cast<const float4*>(&agg[(size_t)row * KD + kg]);
            ainv[j] = 1.f / fmaxf(cnt[row], 1.f);
        } else {
            areg[j] = *reinterpret_cast<const float4*>(&xin[(size_t)row * KD + (kg - KD)]);
            ainv[j] = 1.f;
        }
    }

    for (int kti = 0; kti < NK; kti++) {
        int kt = kti * BK;
        __syncthreads();

#pragma unroll
        for (int j = 0; j < WLD; j++) {
            int idx = tid + j * 256;
            int k = idx / (OD / 4), cq = idx % (OD / 4);
            int kg = kt + k;
            const float* gsrc = (kg < KD) ? &Wl[(size_t)kg * OD + 4 * cq]
                                          : &Wr[(size_t)(kg - KD) * OD + 4 * cq];
            cp_async16(&sW[k * OD + 4 * cq], gsrc);
        }
        asm volatile("cp.async.commit_group;" ::: "memory");

#pragma unroll
        for (int j = 0; j < ALD; j++) {
            int idx = tid + j * 256;
            int m = idx >> 3, kq = idx & 7;
            float iv = ainv[j];
            sA[(4*kq+0) * ASTR + m] = areg[j].x * iv;
            sA[(4*kq+1) * ASTR + m] = areg[j].y * iv;
            sA[(4*kq+2) * ASTR + m] = areg[j].z * iv;
            sA[(4*kq+3) * ASTR + m] = areg[j].w * iv;
        }

        if (kti + 1 < NK) {
            int ktn = kt + BK;
#pragma unroll
            for (int j = 0; j < ALD; j++) {
                int idx = tid + j * 256;
                int m = idx >> 3, kq = idx & 7;
                int row = row0 + m;
                int kg = ktn + 4 * kq;
                if (kg < KD) {
                    areg[j] = *reinterpret_cast<const float4*>(&agg[(size_t)row * KD + kg]);
                    ainv[j] = 1.f / fmaxf(cnt[row], 1.f);
                } else {
                    areg[j] = *reinterpret_cast<const float4*>(&xin[(size_t)row * KD + (kg - KD)]);
                    ainv[j] = 1.f;
                }
            }
        }

        asm volatile("cp.async.wait_group 0;" ::: "memory");
        __syncthreads();

#pragma unroll
        for (int k = 0; k < BK; k++) {
            const ulonglong2* ap2 = reinterpret_cast<const ulonglong2*>(&sA[k * ASTR + ty * 8]);
            ulonglong2 p0 = ap2[0], p1 = ap2[1];
            unsigned long long ap[4] = { p0.x, p0.y, p1.x, p1.y };
#pragma unroll
            for (int jj = 0; jj < TN / 4; jj++) {
                float4 w4 = *reinterpret_cast<const float4*>(&sW[k * OD + tx * TN + jj * 4]);
                unsigned long long w0 = pk2(w4.x, w4.x), w1 = pk2(w4.y, w4.y);
                unsigned long long w2 = pk2(w4.z, w4.z), w3 = pk2(w4.w, w4.w);
#pragma unroll
                for (int r = 0; r < 4; r++) {
                    ffma2(acc[r][jj*4+0], ap[r], w0);
                    ffma2(acc[r][jj*4+1], ap[r], w1);
                    ffma2(acc[r][jj*4+2], ap[r], w2);
                    ffma2(acc[r][jj*4+3], ap[r], w3);
                }
            }
        }
    }

    float cs[TN], cs2[TN];
#pragma unroll
    for (int j = 0; j < TN; j++) { cs[j] = 0.f; cs2[j] = 0.f; }
    float bb[TN];
#pragma unroll
    for (int jj = 0; jj < TN / 4; jj++) {
        float4 b4 = *reinterpret_cast<const float4*>(&bias[tx * TN + jj * 4]);
        bb[jj*4+0]=b4.x; bb[jj*4+1]=b4.y; bb[jj*4+2]=b4.z; bb[jj*4+3]=b4.w;
    }
#pragma unroll
    for (int r = 0; r < 4; r++) {
        float lo[TN], hi[TN];
#pragma unroll
        for (int j = 0; j < TN; j++) {
            upk2(acc[r][j], lo[j], hi[j]);
            lo[j] += bb[j]; hi[j] += bb[j];
            cs[j]  += lo[j] + hi[j];
            cs2[j] += lo[j]*lo[j] + hi[j]*hi[j];
        }
        int row_lo = row0 + ty * 8 + 2 * r;
#pragma unroll
        for (int jj = 0; jj < TN / 4; jj++) {
            int c = tx * TN + jj * 4;
            *reinterpret_cast<float4*>(&outp[(size_t)row_lo * OD + c]) =
                make_float4(lo[jj*4], lo[jj*4+1], lo[jj*4+2], lo[jj*4+3]);
            *reinterpret_cast<float4*>(&outp[(size_t)(row_lo+1) * OD + c]) =
                make_float4(hi[jj*4], hi[jj*4+1], hi[jj*4+2], hi[jj*4+3]);
        }
    }

    __syncthreads();
    float* sRed = sh;
#pragma unroll
    for (int j = 0; j < TN; j++) sRed[ty * OD + tx * TN + j] = cs[j];
    __syncthreads();
    for (int c = tid; c < OD; c += 256) {
        float t = 0.f;
#pragma unroll
        for (int i = 0; i < NTY; i++) t += sRed[i * OD + c];
        atomicAdd(&bnacc[c], t);
    }
    __syncthreads();
#pragma unroll
    for (int j = 0; j < TN; j++) sRed[ty * OD + tx * TN + j] = cs2[j];
    __syncthreads();
    for (int c = tid; c < OD; c += 256) {
        float t = 0.f;
#pragma unroll
        for (int i = 0; i < NTY; i++) t += sRed[i * OD + c];
        atomicAdd(&bnacc[OD + c], t);
    }

    __shared__ int sDone;
    __threadfence();
    if (tid == 0) {
        int old = atomicAdd(ctr, 1);
        sDone = (old == (int)gridDim.x - 1);
    }
    __syncthreads();
    if (sDone) {
        if (tid < OD) {
            float s  = __ldcg(&bnacc[tid]);
            float s2 = __ldcg(&bnacc[OD + tid]);
            float m   = s * invn;
            float var = s2 * invn - m * m;
            float sc  = rsqrtf(var + 1e-5f) * bng[tid];
            scale[tid] = sc;
            shift[tid] = bnb[tid] - m * sc;
        }
        if (tid == 0) *ctr = 0;
    }
}

// fused: BN apply (registers only) + ReLU + two score dot products. One warp per row.
template<int D>
__global__ void bnad_kernel(const float* __restrict__ pre, const float* __restrict__ scale,
                            const float* __restrict__ shift,
                            const float* __restrict__ wrel, const float* __restrict__ wroot,
                            float* __restrict__ rrel, float* __restrict__ rroot, int nrows)
{
    int w = (blockIdx.x * blockDim.x + threadIdx.x) >> 5;
    int lane = threadIdx.x & 31;
    if (w >= nrows) return;
    const int V = D / 128;
    float s1 = 0.f, s2 = 0.f;
    const float4* rowp = reinterpret_cast<const float4*>(pre + (size_t)w * D);
#pragma unroll
    for (int q = 0; q < V; q++) {
        int c4 = lane + q * 32;
        float4 v  = rowp[c4];
        float4 sc = reinterpret_cast<const float4*>(scale)[c4];
        float4 sh = reinterpret_cast<const float4*>(shift)[c4];
        v.x = fmaxf(fmaf(v.x, sc.x, sh.x), 0.f);
        v.y = fmaxf(fmaf(v.y, sc.y, sh.y), 0.f);
        v.z = fmaxf(fmaf(v.z, sc.z, sh.z), 0.f);
        v.w = fmaxf(fmaf(v.w, sc.w, sh.w), 0.f);
        float4 wr = reinterpret_cast<const float4*>(wrel)[c4];
        float4 wo = reinterpret_cast<const float4*>(wroot)[c4];
        s1 += v.x*wr.x + v.y*wr.y + v.z*wr.z + v.w*wr.w;
        s2 += v.x*wo.x + v.y*wo.y + v.z*wo.z + v.w*wo.w;
    }
#pragma unroll
    for (int o = 16; o; o >>= 1) {
        s1 += __shfl_down_sync(0xFFFFFFFFu, s1, o);
        s2 += __shfl_down_sync(0xFFFFFFFFu, s2, o);
    }
    if (lane == 0) { rrel[w] = s1; rroot[w] = s2; }
}

// ================= fused per-graph pool: smem segment-sum + RADIX-SELECT top-K =================
template<int NODES, int KSEL, bool WMAP>
__global__ void __launch_bounds__(1024)
pool_kernel(const float* __restrict__ rrel, const float* __restrict__ rroot,
            const float* __restrict__ brel,
            const int* __restrict__ src, const int* __restrict__ tgt,
            int* __restrict__ perm, float* __restrict__ tanhv,
            int* __restrict__ gmap)
{
    extern __shared__ char shraw[];
    float*    srrel = (float*)shraw;                  // NODES
    float*    sseg  = srrel + NODES;                  // NODES
    unsigned* skey  = (unsigned*)(sseg + NODES);      // NODES
    int*      eqL   = (int*)(skey + NODES);           // NODES
    int*      hist  = eqL + NODES;                    // 256
    int*      sCnt  = hist + 256;                     // 2 counters

    const int g   = blockIdx.x;
    const int tid = threadIdx.x;
    const int lane = tid & 31;
    const int base = g * NODES;
    const float br = brel[0];

    for (int i = tid; i < NODES; i += 1024) {
        srrel[i] = rrel[base + i];
        sseg[i] = 0.f;
    }
    __syncthreads();

    for (int e = tid; e < EPG; e += 1024) {
        int s = src[g * EPG + e];
        if (s < 0) continue;
        int t = tgt[g * EPG + e];
        atomicAdd(&sseg[t - base], srrel[s - base]);
    }
    __syncthreads();

    for (int i = tid; i < NODES; i += 1024) {
        float sc = sseg[i] + br + rroot[base + i];
        unsigned u = __float_as_uint(sc);
        skey[i] = (u & 0x80000000u) ? ~u : (u | 0x80000000u);
    }
    __syncthreads();

    __shared__ unsigned sPrefix;
    __shared__ int sRemain;
    if (tid == 0) { sPrefix = 0u; sRemain = KSEL; }
    __syncthreads();
#pragma unroll
    for (int round = 0; round < 4; round++) {
        const int shift = 24 - 8 * round;
        for (int b = tid; b < 256; b += 1024) hist[b] = 0;
        __syncthreads();
        unsigned prefmask = (round == 0) ? 0u : (0xFFFFFFFFu << (shift + 8));
        unsigned pref = sPrefix;
        for (int i = tid; i < NODES; i += 1024) {
            unsigned k = skey[i];
            if ((k & prefmask) == (pref & prefmask))
                atomicAdd(&hist[(k >> shift) & 255], 1);
        }
        __syncthreads();
        if (tid < 32) {
            int hi = 255 - lane * 8;
            int c[8];
            int lsum = 0;
#pragma unroll
            for (int q = 0; q < 8; q++) { c[q] = hist[hi - q]; lsum += c[q]; }
            int run = lsum;
#pragma unroll
            for (int o = 1; o < 32; o <<= 1) {
                int v = __shfl_up_sync(0xFFFFFFFFu, run, o);
                if (lane >= o) run += v;
            }
            int pre = run - lsum;
            int rem = sRemain;
            __syncwarp();
            int running = pre;
#pragma unroll
            for (int q = 0; q < 8; q++) {
                if (rem > running && rem <= running + c[q]) {
                    sRemain = rem - running;
                    sPrefix = pref | ((unsigned)(hi - q) << shift);
                }
                running += c[q];
            }
        }
        __syncthreads();
    }
    const unsigned T = sPrefix;
    const int R = sRemain;

    if (tid == 0) { sCnt[0] = 0; sCnt[1] = 0; }
    __syncthreads();

    for (int i = tid; i < NODES; i += 1024) {
        unsigned k = skey[i];
        if (k > T) {
            int slot = atomicAdd(&sCnt[0], 1);
            unsigned u = (k & 0x80000000u) ? (k & 0x7FFFFFFFu) : ~k;
            float sc = __uint_as_float(u);
            perm[g * KSEL + slot]  = base + i;
            tanhv[g * KSEL + slot] = tanhf(sc);
            if (WMAP) gmap[base + i] = g * KSEL + slot;
        } else if (k == T) {
            int e = atomicAdd(&sCnt[1], 1);
            eqL[e] = i;
        }
    }
    __syncthreads();
    const int neq = sCnt[1];
    for (int j = tid; j < neq; j += 1024) {
        int i = eqL[j];
        int rank = 0;
        for (int l = 0; l < neq; l++) rank += (eqL[l] > i);
        if (rank < R) {
            int slot = atomicAdd(&sCnt[0], 1);
            unsigned u = (T & 0x80000000u) ? (T & 0x7FFFFFFFu) : ~T;
            float sc = __uint_as_float(u);
            perm[g * KSEL + slot]  = base + i;
            tanhv[g * KSEL + slot] = tanhf(sc);
            if (WMAP) gmap[base + i] = g * KSEL + slot;
        }
    }
}

// full-chip edge remap via global map
__global__ void remap_kernel(const int* __restrict__ src, const int* __restrict__ tgt,
                             const int* __restrict__ mapping,
                             int* __restrict__ src2, int* __restrict__ tgt2)
{
    int e = blockIdx.x * blockDim.x + threadIdx.x;
    if (e >= Ee) return;
    int s = mapping[src[e]];
    int t = mapping[tgt[e]];
    if (s < 0 || t < 0) { s = -1; t = -1; }
    src2[e] = s; tgt2[e] = t;
}

// gather + BN/ReLU + tanh-scale (float4), full-chip
__global__ void gather_kernel(const float* __restrict__ pre, const int* __restrict__ perm,
                              const float* __restrict__ scale, const float* __restrict__ shift,
                              const float* __restrict__ tv, float* __restrict__ o, int n)
{
    const int V = H1 / 4;  // 32
    int i = blockIdx.x * blockDim.x + threadIdx.x;
    if (i >= n * V) return;
    int node = i / V, off = i - node * V;
    float4 v  = reinterpret_cast<const float4*>(pre)[(size_t)perm[node] * V + off];
    float4 sc = reinterpret_cast<const float4*>(scale)[off];
    float4 sh = reinterpret_cast<const float4*>(shift)[off];
    float t = tv[node];
    v.x = fmaxf(fmaf(v.x, sc.x, sh.x), 0.f) * t;
    v.y = fmaxf(fmaf(v.y, sc.y, sh.y), 0.f) * t;
    v.z = fmaxf(fmaf(v.z, sc.z, sh.z), 0.f) * t;
    v.w = fmaxf(fmaf(v.w, sc.w, sh.w), 0.f) * t;
    reinterpret_cast<float4*>(o)[i] = v;
}

// readout part 1: partial per-graph column sums (8 chunks/graph, full-chip)
__global__ void final_part1(const float* __restrict__ pre2, const int* __restrict__ perm2,
                            const float* __restrict__ scale, const float* __restrict__ shift,
                            const float* __restrict__ tanhv2, float* __restrict__ gacc)
{
    int g = blockIdx.x >> 3;
    int chunk = blockIdx.x & 7;
    int c = threadIdx.x;   // 256
    __shared__ int   sp[64];
    __shared__ float st[64];
    int r0 = chunk * 64;
    if (c < 64) {
        sp[c] = perm2[g * K2 + r0 + c];
        st[c] = tanhv2[g * K2 + r0 + c];
    }
    __syncthreads();
    float sc = scale[c], sh = shift[c];
    float acc = 0.f;
#pragma unroll 8
    for (int r = 0; r < 64; r++)
        acc += fmaxf(fmaf(pre2[(size_t)sp[r] * H2 + c], sc, sh), 0.f) * st[r];
    atomicAdd(&gacc[g * H2 + c], acc);
}

// readout part 2: pooled mean -> relu -> 256x2 linear -> softmax
__global__ void final_part2(const float* __restrict__ gacc, const float* __restrict__ Wlin,
                            const float* __restrict__ blin, float* __restrict__ outp)
{
    int g = blockIdx.x, c = threadIdx.x;   // 256 threads
    float p = fmaxf(gacc[g * H2 + c] * (1.0f / (float)K2), 0.f);
    __shared__ float red0[256], red1[256];
    red0[c] = p * Wlin[c * 2 + 0];
    red1[c] = p * Wlin[c * 2 + 1];
    __syncthreads();
    for (int s = 128; s; s >>= 1) {
        if (c < s) { red0[c] += red0[c + s]; red1[c] += red1[c + s]; }
        __syncthreads();
    }
    if (c == 0) {
        float a = red0[0] + blin[0];
        float b = red1[0] + blin[1];
        float m = fmaxf(a, b);
        float ea = expf(a - m), eb = expf(b - m);
        float inv = 1.f / (ea + eb);
        outp[g * 2 + 0] = ea * inv;
        outp[g * 2 + 1] = eb * inv;
    }
}

// ---------------- host launch ----------------
template <typename T>
static void* symaddr(const T& s) { void* p = nullptr; cudaGetSymbolAddress(&p, s); return p; }

#define POOL1_SMEM (NPG*4*4 + 256*4 + 8)   // ~33.8KB
#define POOL2_SMEM (K1*4*4 + 256*4 + 8)    // ~17.4KB

extern "C" void kernel_launch(void* const* d_in, const int* in_sizes, int n_in,
                              void* d_out, int out_size)
{
    const float* x     = (const float*)d_in[0];
    const int*   ei    = (const int*)  d_in[1];
    const int*   src   = ei;
    const int*   tgt   = ei + Ee;
    const float* W1l   = (const float*)d_in[3];
    const float* b1l   = (const float*)d_in[4];
    const float* W1r   = (const float*)d_in[5];
    const float* bn1g  = (const float*)d_in[6];
    const float* bn1b  = (const float*)d_in[7];
    const float* p1Wrel  = (const float*)d_in[8];
    const float* p1brel  = (const float*)d_in[9];
    const float* p1Wroot = (const float*)d_in[10];
    const float* W2l   = (const float*)d_in[11];
    const float* b2l   = (const float*)d_in[12];
    const float* W2r   = (const float*)d_in[13];
    const float* bn2g  = (const float*)d_in[14];
    const float* bn2b  = (const float*)d_in[15];
    const float* p2Wrel  = (const float*)d_in[16];
    const float* p2brel  = (const float*)d_in[17];
    const float* p2Wroot = (const float*)d_in[18];
    const float* Wlin  = (const float*)d_in[19];
    const float* blin  = (const float*)d_in[20];
    float* out = (float*)d_out;

    float* z1    = (float*)symaddr(g_z1);
    float* agg1  = z1;
    float* cnt1  = z1 + Nn*IND;
    float* bnacc1= cnt1 + Nn;
    float* z2    = (float*)symaddr(g_z2);
    float* agg2  = z2;
    float* cnt2  = z2 + N1*H1;
    float* bnacc2= cnt2 + N1;
    float* gacc  = bnacc2 + 2*H2;

    float* pre1  = (float*)symaddr(g_pre1);
    int*   map1  = (int*)  symaddr(g_map1);
    int*   src2  = (int*)  symaddr(g_src2);
    int*   tgt2  = (int*)  symaddr(g_tgt2);
    float* h1new = (float*)symaddr(g_h1new);
    float* pre2  = (float*)symaddr(g_pre2);
    float* rrel  = (float*)symaddr(g_rrel);
    float* rroot = (float*)symaddr(g_rroot);
    int*   perm1 = (int*)  symaddr(g_perm1);
    float* tanh1 = (float*)symaddr(g_tanh1);
    int*   perm2 = (int*)  symaddr(g_perm2);
    float* tanh2 = (float*)symaddr(g_tanh2);
    float* scale = (float*)symaddr(g_scale);
    float* shift = (float*)symaddr(g_shift);
    int*   ctr1  = (int*)  symaddr(g_ctr1);
    int*   ctr2  = (int*)  symaddr(g_ctr2);

    cudaFuncSetAttribute((const void*)gemm_dual7<IND, H1, 128, 16>,
                         cudaFuncAttributeMaxDynamicSharedMemorySize, 33280);
    cudaFuncSetAttribute((const void*)gemm_dual7<H1, H2, 64, 32>,
                         cudaFuncAttributeMaxDynamicSharedMemorySize, 41472);
    cudaFuncSetAttribute((const void*)pool_kernel<NPG, K1, true>,
                         cudaFuncAttributeMaxDynamicSharedMemorySize, POOL1_SMEM);
    cudaFuncSetAttribute((const void*)pool_kernel<K1, K2, false>,
                         cudaFuncAttributeMaxDynamicSharedMemorySize, POOL2_SMEM);

    // ---- zero-fill (all up front) ----
    cudaMemsetAsync(z1, 0, sizeof(float)*Z1_FLOATS);
    cudaMemsetAsync(z2, 0, sizeof(float)*Z2_FLOATS);
    cudaMemsetAsync(map1, 0xFF, sizeof(int)*Nn);   // -1

    // ---- stage 1 ----
    agg_kernel<IND><<<AGG_BLOCKS, 256>>>(src, tgt, x, agg1, cnt1, Ee);
    gemm_dual7<IND, H1, 128, 16><<<Nn/128, 256, 33280>>>(
        agg1, cnt1, x, W1l, W1r, b1l, pre1,
        bnacc1, ctr1, bn1g, bn1b, scale, shift, 1.f/(float)Nn);
    bnad_kernel<H1><<<Nn/8, 256>>>(pre1, scale, shift, p1Wrel, p1Wroot, rrel, rroot, Nn);
    pool_kernel<NPG, K1, true><<<Bg, 1024, POOL1_SMEM>>>(
        rrel, rroot, p1brel, src, tgt, perm1, tanh1, map1);
    remap_kernel<<<Ee/256, 256>>>(src, tgt, map1, src2, tgt2);
    gather_kernel<<<(N1*(H1/4))/256, 256>>>(pre1, perm1, scale, shift, tanh1, h1new, N1);

    // ---- stage 2 ----
    agg_kernel<H1><<<AGG_BLOCKS, 256>>>(src2, tgt2, h1new, agg2, cnt2, Ee);
    gemm_dual7<H1, H2, 64, 32><<<N1/64, 256, 41472>>>(
        agg2, cnt2, h1new, W2l, W2r, b2l, pre2,
        bnacc2, ctr2, bn2g, bn2b, scale, shift, 1.f/(float)N1);
    bnad_kernel<H2><<<N1/8, 256>>>(pre2, scale, shift, p2Wrel, p2Wroot, rrel, rroot, N1);
    pool_kernel<K1, K2, false><<<Bg, 1024, POOL2_SMEM>>>(
        rrel, rroot, p2brel, src2, tgt2, perm2, tanh2, nullptr);

    // ---- readout (split: partial sums full-chip, then tiny finish) ----
    final_part1<<<Bg*8, 256>>>(pre2, perm2, scale, shift, tanh2, gacc);
    final_part2<<<Bg, 256>>>(gacc, Wlin, blin, out);

    (void)in_sizes; (void)n_in; (void)out_size;
}

// round 16
// speedup vs baseline: 2.1738x; 1.0535x over previous
#include <cuda_runtime.h>
#include <math.h>

// ---------------- problem constants ----------------
#define Bg   32
#define NPG  2048
#define Nn   (Bg*NPG)        // 65536
#define Ee   (Nn*8)          // 524288
#define IND  64
#define H1   128
#define H2   256
#define K1   1024
#define K2   512
#define N1   (Bg*K1)         // 32768
#define N2   (Bg*K2)         // 16384

#define AGG_BLOCKS 2368      // 16 CTAs/SM x 148 SMs, grid-stride

// ---------------- scratch (device globals; no allocs) ----------------
#define Z1_FLOATS (Nn*IND + Nn + Nn + 2*H1)
__device__ float g_z1[Z1_FLOATS];    // [agg1 | cnt1 | sseg1 | bnacc1]
#define Z2_FLOATS (N1*H1 + N1 + N1 + 2*H2 + Bg*H2)
__device__ float g_z2[Z2_FLOATS];    // [agg2 | cnt2 | sseg2 | bnacc2 | gacc]

__device__ float g_pre1 [Nn*H1];
__device__ int   g_map1 [Nn];
__device__ int   g_src2 [Ee];
__device__ int   g_tgt2 [Ee];
__device__ float g_h1new[N1*H1];
__device__ float g_pre2 [N1*H2];
__device__ float g_rrel [Nn];
__device__ float g_rroot[Nn];
__device__ int   g_perm1[N1];
__device__ float g_tanh1[N1];
__device__ int   g_perm2[N2];
__device__ float g_tanh2[N2];
__device__ float g_scale[H2];
__device__ float g_shift[H2];
__device__ int   g_ctr1 = 0;
__device__ int   g_ctr2 = 0;

// ---------------- helpers ----------------
__device__ __forceinline__ unsigned long long pk2(float lo, float hi) {
    unsigned long long r;
    asm("mov.b64 %0, {%1,%2};" : "=l"(r) : "f"(lo), "f"(hi));
    return r;
}
__device__ __forceinline__ void upk2(unsigned long long v, float& lo, float& hi) {
    asm("mov.b64 {%0,%1}, %2;" : "=f"(lo), "=f"(hi) : "l"(v));
}
__device__ __forceinline__ void ffma2(unsigned long long& d, unsigned long long a, unsigned long long b) {
    asm("fma.rn.f32x2 %0, %1, %2, %0;" : "+l"(d) : "l"(a), "l"(b));
}
__device__ __forceinline__ void cp_async16(float* smem, const float* gmem) {
    unsigned saddr = (unsigned)__cvta_generic_to_shared(smem);
    asm volatile("cp.async.cg.shared.global [%0], [%1], 16;" :: "r"(saddr), "l"(gmem) : "memory");
}

// ---------------- kernels ----------------

// grid-stride mean aggregation: one (edge, float4) work item per loop step
template<int D>
__global__ void agg_kernel(const int* __restrict__ src, const int* __restrict__ tgt,
                           const float* __restrict__ xin, float* __restrict__ aggo,
                           float* __restrict__ cnt, int nedges)
{
    const int V = D / 4;
    const int total = nedges * V;
    const int stride = gridDim.x * blockDim.x;
    for (int i = blockIdx.x * blockDim.x + threadIdx.x; i < total; i += stride) {
        int e  = i / V;
        int f4 = i - e * V;
        int s = src[e];
        if (s < 0) continue;
        int t = tgt[e];
        float4 v = reinterpret_cast<const float4*>(xin)[(size_t)s * V + f4];
        asm volatile("red.global.add.v4.f32 [%0], {%1,%2,%3,%4};"
                     :: "l"(&aggo[(size_t)t * D + f4 * 4]),
                        "f"(v.x), "f"(v.y), "f"(v.z), "f"(v.w) : "memory");
        if (f4 == 0) atomicAdd(&cnt[t], 1.0f);
    }
}

// pre[n,OD] = (agg[n]/max(cnt,1)) @ Wl + xin @ Wr + bias   (K concat, FFMA2)
// A read as packed ulonglong2 row-pairs. W via cp.async (float4 + broadcast movs).
// Epilogue: per-column sum/sumsq into bnacc; last block computes scale/shift.
template<int KD, int OD, int BM, int CG>
__global__ void __launch_bounds__(256)
gemm_dual7(const float* __restrict__ agg, const float* __restrict__ cnt,
           const float* __restrict__ xin,
           const float* __restrict__ Wl, const float* __restrict__ Wr,
           const float* __restrict__ bias, float* __restrict__ outp,
           float* __restrict__ bnacc, int* __restrict__ ctr,
           const float* __restrict__ bng, const float* __restrict__ bnb,
           float* __restrict__ scale, float* __restrict__ shift,
           float invn)
{
    const int TN = 8, BK = 32, ASTR = BM + 4;
    const int NTY = 256 / CG;
    const int NK  = 2 * KD / BK;
    const int ALD = BM * BK / (4 * 256);
    const int WLD = BK * OD / (4 * 256);
    extern __shared__ float sh[];
    float* sW = sh;
    float* sA = sh + BK * OD;

    int tid = threadIdx.x;
    int tx  = tid % CG;
    int ty  = tid / CG;
    int row0 = blockIdx.x * BM;

    unsigned long long acc[4][TN];
#pragma unroll
    for (int r = 0; r < 4; r++)
#pragma unroll
        for (int j = 0; j < TN; j++) acc[r][j] = 0ull;

    float4 areg[ALD];
    float  ainv[ALD];

#pragma unroll
    for (int j = 0; j < ALD; j++) {
        int idx = tid + j * 256;
        int m = idx >> 3, kq = idx & 7;
        int row = row0 + m;
        int kg = 4 * kq;
        if (kg < KD) {
            areg[j] = *reinterpret_cast<const float4*>(&agg[(size_t)row * KD + kg]);
            ainv[j] = 1.f / fmaxf(cnt[row], 1.f);
        } else {
            areg[j] = *reinterpret_cast<const float4*>(&xin[(size_t)row * KD + (kg - KD)]);
            ainv[j] = 1.f;
        }
    }

    for (int kti = 0; kti < NK; kti++) {
        int kt = kti * BK;
        __syncthreads();

#pragma unroll
        for (int j = 0; j < WLD; j++) {
            int idx = tid + j * 256;
            int k = idx / (OD / 4), cq = idx % (OD / 4);
            int kg = kt + k;
            const float* gsrc = (kg < KD) ? &Wl[(size_t)kg * OD + 4 * cq]
                                          : &Wr[(size_t)(kg - KD) * OD + 4 * cq];
            cp_async16(&sW[k * OD + 4 * cq], gsrc);
        }
        asm volatile("cp.async.commit_group;" ::: "memory");

#pragma unroll
        for (int j = 0; j < ALD; j++) {
            int idx = tid + j * 256;
            int m = idx >> 3, kq = idx & 7;
            float iv = ainv[j];
            sA[(4*kq+0) * ASTR + m] = areg[j].x * iv;
            sA[(4*kq+1) * ASTR + m] = areg[j].y * iv;
            sA[(4*kq+2) * ASTR + m] = areg[j].z * iv;
            sA[(4*kq+3) * ASTR + m] = areg[j].w * iv;
        }

        if (kti + 1 < NK) {
            int ktn = kt + BK;
#pragma unroll
            for (int j = 0; j < ALD; j++) {
                int idx = tid + j * 256;
                int m = idx >> 3, kq = idx & 7;
                int row = row0 + m;
                int kg = ktn + 4 * kq;
                if (kg < KD) {
                    areg[j] = *reinterpret_cast<const float4*>(&agg[(size_t)row * KD + kg]);
                    ainv[j] = 1.f / fmaxf(cnt[row], 1.f);
                } else {
                    areg[j] = *reinterpret_cast<const float4*>(&xin[(size_t)row * KD + (kg - KD)]);
                    ainv[j] = 1.f;
                }
            }
        }

        asm volatile("cp.async.wait_group 0;" ::: "memory");
        __syncthreads();

#pragma unroll
        for (int k = 0; k < BK; k++) {
            const ulonglong2* ap2 = reinterpret_cast<const ulonglong2*>(&sA[k * ASTR + ty * 8]);
            ulonglong2 p0 = ap2[0], p1 = ap2[1];
            unsigned long long ap[4] = { p0.x, p0.y, p1.x, p1.y };
#pragma unroll
            for (int jj = 0; jj < TN / 4; jj++) {
                float4 w4 = *reinterpret_cast<const float4*>(&sW[k * OD + tx * TN + jj * 4]);
                unsigned long long w0 = pk2(w4.x, w4.x), w1 = pk2(w4.y, w4.y);
                unsigned long long w2 = pk2(w4.z, w4.z), w3 = pk2(w4.w, w4.w);
#pragma unroll
                for (int r = 0; r < 4; r++) {
                    ffma2(acc[r][jj*4+0], ap[r], w0);
                    ffma2(acc[r][jj*4+1], ap[r], w1);
                    ffma2(acc[r][jj*4+2], ap[r], w2);
                    ffma2(acc[r][jj*4+3], ap[r], w3);
                }
            }
        }
    }

    float cs[TN], cs2[TN];
#pragma unroll
    for (int j = 0; j < TN; j++) { cs[j] = 0.f; cs2[j] = 0.f; }
    float bb[TN];
#pragma unroll
    for (int jj = 0; jj < TN / 4; jj++) {
        float4 b4 = *reinterpret_cast<const float4*>(&bias[tx * TN + jj * 4]);
        bb[jj*4+0]=b4.x; bb[jj*4+1]=b4.y; bb[jj*4+2]=b4.z; bb[jj*4+3]=b4.w;
    }
#pragma unroll
    for (int r = 0; r < 4; r++) {
        float lo[TN], hi[TN];
#pragma unroll
        for (int j = 0; j < TN; j++) {
            upk2(acc[r][j], lo[j], hi[j]);
            lo[j] += bb[j]; hi[j] += bb[j];
            cs[j]  += lo[j] + hi[j];
            cs2[j] += lo[j]*lo[j] + hi[j]*hi[j];
        }
        int row_lo = row0 + ty * 8 + 2 * r;
#pragma unroll
        for (int jj = 0; jj < TN / 4; jj++) {
            int c = tx * TN + jj * 4;
            *reinterpret_cast<float4*>(&outp[(size_t)row_lo * OD + c]) =
                make_float4(lo[jj*4], lo[jj*4+1], lo[jj*4+2], lo[jj*4+3]);
            *reinterpret_cast<float4*>(&outp[(size_t)(row_lo+1) * OD + c]) =
                make_float4(hi[jj*4], hi[jj*4+1], hi[jj*4+2], hi[jj*4+3]);
        }
    }

    __syncthreads();
    float* sRed = sh;
#pragma unroll
    for (int j = 0; j < TN; j++) sRed[ty * OD + tx * TN + j] = cs[j];
    __syncthreads();
    for (int c = tid; c < OD; c += 256) {
        float t = 0.f;
#pragma unroll
        for (int i = 0; i < NTY; i++) t += sRed[i * OD + c];
        atomicAdd(&bnacc[c], t);
    }
    __syncthreads();
#pragma unroll
    for (int j = 0; j < TN; j++) sRed[ty * OD + tx * TN + j] = cs2[j];
    __syncthreads();
    for (int c = tid; c < OD; c += 256) {
        float t = 0.f;
#pragma unroll
        for (int i = 0; i < NTY; i++) t += sRed[i * OD + c];
        atomicAdd(&bnacc[OD + c], t);
    }

    __shared__ int sDone;
    __threadfence();
    if (tid == 0) {
        int old = atomicAdd(ctr, 1);
        sDone = (old == (int)gridDim.x - 1);
    }
    __syncthreads();
    if (sDone) {
        if (tid < OD) {
            float s  = __ldcg(&bnacc[tid]);
            float s2 = __ldcg(&bnacc[OD + tid]);
            float m   = s * invn;
            float var = s2 * invn - m * m;
            float sc  = rsqrtf(var + 1e-5f) * bng[tid];
            scale[tid] = sc;
            shift[tid] = bnb[tid] - m * sc;
        }
        if (tid == 0) *ctr = 0;
    }
}

// fused: BN apply (registers only) + ReLU + two score dot products. One warp per row.
template<int D>
__global__ void bnad_kernel(const float* __restrict__ pre, const float* __restrict__ scale,
                            const float* __restrict__ shift,
                            const float* __restrict__ wrel, const float* __restrict__ wroot,
                            float* __restrict__ rrel, float* __restrict__ rroot, int nrows)
{
    int w = (blockIdx.x * blockDim.x + threadIdx.x) >> 5;
    int lane = threadIdx.x & 31;
    if (w >= nrows) return;
    const int V = D / 128;
    float s1 = 0.f, s2 = 0.f;
    const float4* rowp = reinterpret_cast<const float4*>(pre + (size_t)w * D);
#pragma unroll
    for (int q = 0; q < V; q++) {
        int c4 = lane + q * 32;
        float4 v  = rowp[c4];
        float4 sc = reinterpret_cast<const float4*>(scale)[c4];
        float4 sh = reinterpret_cast<const float4*>(shift)[c4];
        v.x = fmaxf(fmaf(v.x, sc.x, sh.x), 0.f);
        v.y = fmaxf(fmaf(v.y, sc.y, sh.y), 0.f);
        v.z = fmaxf(fmaf(v.z, sc.z, sh.z), 0.f);
        v.w = fmaxf(fmaf(v.w, sc.w, sh.w), 0.f);
        float4 wr = reinterpret_cast<const float4*>(wrel)[c4];
        float4 wo = reinterpret_cast<const float4*>(wroot)[c4];
        s1 += v.x*wr.x + v.y*wr.y + v.z*wr.z + v.w*wr.w;
        s2 += v.x*wo.x + v.y*wo.y + v.z*wo.z + v.w*wo.w;
    }
#pragma unroll
    for (int o = 16; o; o >>= 1) {
        s1 += __shfl_down_sync(0xFFFFFFFFu, s1, o);
        s2 += __shfl_down_sync(0xFFFFFFFFu, s2, o);
    }
    if (lane == 0) { rrel[w] = s1; rroot[w] = s2; }
}

// full-chip grid-stride GraphConv segment-sum: sseg[tgt] += rrel[src]
template<bool MASK>
__global__ void escore_kernel(const int* __restrict__ src, const int* __restrict__ tgt,
                              const float* __restrict__ rrel, float* __restrict__ sseg)
{
    const int stride = gridDim.x * blockDim.x;
    for (int e = blockIdx.x * blockDim.x + threadIdx.x; e < Ee; e += stride) {
        int s = src[e];
        if (MASK && s < 0) continue;
        atomicAdd(&sseg[tgt[e]], rrel[s]);
    }
}

// ================= per-graph RADIX-SELECT top-K (scores precomputed) =================
template<int NODES, int KSEL, bool WMAP>
__global__ void __launch_bounds__(1024)
pool_kernel(const float* __restrict__ sseg, const float* __restrict__ rroot,
            const float* __restrict__ brel,
            int* __restrict__ perm, float* __restrict__ tanhv,
            int* __restrict__ gmap)
{
    extern __shared__ char shraw[];
    unsigned* skey  = (unsigned*)shraw;               // NODES
    int*      eqL   = (int*)(skey + NODES);           // NODES
    int*      hist  = eqL + NODES;                    // 256
    int*      sCnt  = hist + 256;                     // 2 counters

    const int g   = blockIdx.x;
    const int tid = threadIdx.x;
    const int lane = tid & 31;
    const int base = g * NODES;
    const float br = brel[0];

    // key build (monotone map of score)
    for (int i = tid; i < NODES; i += 1024) {
        float sc = sseg[base + i] + br + rroot[base + i];
        unsigned u = __float_as_uint(sc);
        skey[i] = (u & 0x80000000u) ? ~u : (u | 0x80000000u);
    }
    __syncthreads();

    // radix-select the KSEL-th largest key (4 x 8-bit rounds); warp-0 scan picks bin
    __shared__ unsigned sPrefix;
    __shared__ int sRemain;
    if (tid == 0) { sPrefix = 0u; sRemain = KSEL; }
    __syncthreads();
#pragma unroll
    for (int round = 0; round < 4; round++) {
        const int shift = 24 - 8 * round;
        for (int b = tid; b < 256; b += 1024) hist[b] = 0;
        __syncthreads();
        unsigned prefmask = (round == 0) ? 0u : (0xFFFFFFFFu << (shift + 8));
        unsigned pref = sPrefix;
        for (int i = tid; i < NODES; i += 1024) {
            unsigned k = skey[i];
            if ((k & prefmask) == (pref & prefmask))
                atomicAdd(&hist[(k >> shift) & 255], 1);
        }
        __syncthreads();
        if (tid < 32) {
            int hi = 255 - lane * 8;
            int c[8];
            int lsum = 0;
#pragma unroll
            for (int q = 0; q < 8; q++) { c[q] = hist[hi - q]; lsum += c[q]; }
            int run = lsum;
#pragma unroll
            for (int o = 1; o < 32; o <<= 1) {
                int v = __shfl_up_sync(0xFFFFFFFFu, run, o);
                if (lane >= o) run += v;
            }
            int pre = run - lsum;
            int rem = sRemain;
            __syncwarp();
            int running = pre;
#pragma unroll
            for (int q = 0; q < 8; q++) {
                if (rem > running && rem <= running + c[q]) {
                    sRemain = rem - running;
                    sPrefix = pref | ((unsigned)(hi - q) << shift);
                }
                running += c[q];
            }
        }
        __syncthreads();
    }
    const unsigned T = sPrefix;
    const int R = sRemain;

    if (tid == 0) { sCnt[0] = 0; sCnt[1] = 0; }
    __syncthreads();

    // selection & output (slot order irrelevant)
    for (int i = tid; i < NODES; i += 1024) {
        unsigned k = skey[i];
        if (k > T) {
            int slot = atomicAdd(&sCnt[0], 1);
            unsigned u = (k & 0x80000000u) ? (k & 0x7FFFFFFFu) : ~k;
            float sc = __uint_as_float(u);
            perm[g * KSEL + slot]  = base + i;
            tanhv[g * KSEL + slot] = tanhf(sc);
            if (WMAP) gmap[base + i] = g * KSEL + slot;
        } else if (k == T) {
            int e = atomicAdd(&sCnt[1], 1);
            eqL[e] = i;
        }
    }
    __syncthreads();
    const int neq = sCnt[1];
    for (int j = tid; j < neq; j += 1024) {
        int i = eqL[j];
        int rank = 0;
        for (int l = 0; l < neq; l++) rank += (eqL[l] > i);
        if (rank < R) {
            int slot = atomicAdd(&sCnt[0], 1);
            unsigned u = (T & 0x80000000u) ? (T & 0x7FFFFFFFu) : ~T;
            float sc = __uint_as_float(u);
            perm[g * KSEL + slot]  = base + i;
            tanhv[g * KSEL + slot] = tanhf(sc);
            if (WMAP) gmap[base + i] = g * KSEL + slot;
        }
    }
}

// merged: gather (blocks [0, GB)) + edge remap (blocks [GB, GB+RB))
#define GATHER_BLOCKS ((N1*(H1/4))/256)   // 4096
#define REMAP_BLOCKS  (Ee/256)            // 2048
__global__ void scatter_kernel(const float* __restrict__ pre, const int* __restrict__ perm,
                               const float* __restrict__ scale, const float* __restrict__ shift,
                               const float* __restrict__ tv, float* __restrict__ o,
                               const int* __restrict__ src, const int* __restrict__ tgt,
                               const int* __restrict__ mapping,
                               int* __restrict__ src2, int* __restrict__ tgt2)
{
    if (blockIdx.x < GATHER_BLOCKS) {
        const int V = H1 / 4;  // 32
        int i = blockIdx.x * blockDim.x + threadIdx.x;
        int node = i / V, off = i - node * V;
        float4 v  = reinterpret_cast<const float4*>(pre)[(size_t)perm[node] * V + off];
        float4 sc = reinterpret_cast<const float4*>(scale)[off];
        float4 sh = reinterpret_cast<const float4*>(shift)[off];
        float t = tv[node];
        v.x = fmaxf(fmaf(v.x, sc.x, sh.x), 0.f) * t;
        v.y = fmaxf(fmaf(v.y, sc.y, sh.y), 0.f) * t;
        v.z = fmaxf(fmaf(v.z, sc.z, sh.z), 0.f) * t;
        v.w = fmaxf(fmaf(v.w, sc.w, sh.w), 0.f) * t;
        reinterpret_cast<float4*>(o)[i] = v;
    } else {
        int e = (blockIdx.x - GATHER_BLOCKS) * blockDim.x + threadIdx.x;
        int s = mapping[src[e]];
        int t = mapping[tgt[e]];
        if (s < 0 || t < 0) { s = -1; t = -1; }
        src2[e] = s; tgt2[e] = t;
    }
}

// readout part 1: partial per-graph column sums (8 chunks/graph, full-chip)
__global__ void final_part1(const float* __restrict__ pre2, const int* __restrict__ perm2,
                            const float* __restrict__ scale, const float* __restrict__ shift,
                            const float* __restrict__ tanhv2, float* __restrict__ gacc)
{
    int g = blockIdx.x >> 3;
    int chunk = blockIdx.x & 7;
    int c = threadIdx.x;   // 256
    __shared__ int   sp[64];
    __shared__ float st[64];
    int r0 = chunk * 64;
    if (c < 64) {
        sp[c] = perm2[g * K2 + r0 + c];
        st[c] = tanhv2[g * K2 + r0 + c];
    }
    __syncthreads();
    float sc = scale[c], sh = shift[c];
    float acc = 0.f;
#pragma unroll 8
    for (int r = 0; r < 64; r++)
        acc += fmaxf(fmaf(pre2[(size_t)sp[r] * H2 + c], sc, sh), 0.f) * st[r];
    atomicAdd(&gacc[g * H2 + c], acc);
}

// readout part 2: pooled mean -> relu -> 256x2 linear -> softmax
__global__ void final_part2(const float* __restrict__ gacc, const float* __restrict__ Wlin,
                            const float* __restrict__ blin, float* __restrict__ outp)
{
    int g = blockIdx.x, c = threadIdx.x;   // 256 threads
    float p = fmaxf(gacc[g * H2 + c] * (1.0f / (float)K2), 0.f);
    __shared__ float red0[256], red1[256];
    red0[c] = p * Wlin[c * 2 + 0];
    red1[c] = p * Wlin[c * 2 + 1];
    __syncthreads();
    for (int s = 128; s; s >>= 1) {
        if (c < s) { red0[c] += red0[c + s]; red1[c] += red1[c + s]; }
        __syncthreads();
    }
    if (c == 0) {
        float a = red0[0] + blin[0];
        float b = red1[0] + blin[1];
        float m = fmaxf(a, b);
        float ea = expf(a - m), eb = expf(b - m);
        float inv = 1.f / (ea + eb);
        outp[g * 2 + 0] = ea * inv;
        outp[g * 2 + 1] = eb * inv;
    }
}

// ---------------- host launch ----------------
template <typename T>
static void* symaddr(const T& s) { void* p = nullptr; cudaGetSymbolAddress(&p, s); return p; }

#define POOL1_SMEM (NPG*4*2 + 256*4 + 8)   // ~17.4KB
#define POOL2_SMEM (K1*4*2 + 256*4 + 8)    // ~9.2KB

extern "C" void kernel_launch(void* const* d_in, const int* in_sizes, int n_in,
                              void* d_out, int out_size)
{
    const float* x     = (const float*)d_in[0];
    const int*   ei    = (const int*)  d_in[1];
    const int*   src   = ei;
    const int*   tgt   = ei + Ee;
    const float* W1l   = (const float*)d_in[3];
    const float* b1l   = (const float*)d_in[4];
    const float* W1r   = (const float*)d_in[5];
    const float* bn1g  = (const float*)d_in[6];
    const float* bn1b  = (const float*)d_in[7];
    const float* p1Wrel  = (const float*)d_in[8];
    const float* p1brel  = (const float*)d_in[9];
    const float* p1Wroot = (const float*)d_in[10];
    const float* W2l   = (const float*)d_in[11];
    const float* b2l   = (const float*)d_in[12];
    const float* W2r   = (const float*)d_in[13];
    const float* bn2g  = (const float*)d_in[14];
    const float* bn2b  = (const float*)d_in[15];
    const float* p2Wrel  = (const float*)d_in[16];
    const float* p2brel  = (const float*)d_in[17];
    const float* p2Wroot = (const float*)d_in[18];
    const float* Wlin  = (const float*)d_in[19];
    const float* blin  = (const float*)d_in[20];
    float* out = (float*)d_out;

    float* z1    = (float*)symaddr(g_z1);
    float* agg1  = z1;
    float* cnt1  = z1 + Nn*IND;
    float* sseg1 = cnt1 + Nn;
    float* bnacc1= sseg1 + Nn;
    float* z2    = (float*)symaddr(g_z2);
    float* agg2  = z2;
    float* cnt2  = z2 + N1*H1;
    float* sseg2 = cnt2 + N1;
    float* bnacc2= sseg2 + N1;
    float* gacc  = bnacc2 + 2*H2;

    float* pre1  = (float*)symaddr(g_pre1);
    int*   map1  = (int*)  symaddr(g_map1);
    int*   src2  = (int*)  symaddr(g_src2);
    int*   tgt2  = (int*)  symaddr(g_tgt2);
    float* h1new = (float*)symaddr(g_h1new);
    float* pre2  = (float*)symaddr(g_pre2);
    float* rrel  = (float*)symaddr(g_rrel);
    float* rroot = (float*)symaddr(g_rroot);
    int*   perm1 = (int*)  symaddr(g_perm1);
    float* tanh1 = (float*)symaddr(g_tanh1);
    int*   perm2 = (int*)  symaddr(g_perm2);
    float* tanh2 = (float*)symaddr(g_tanh2);
    float* scale = (float*)symaddr(g_scale);
    float* shift = (float*)symaddr(g_shift);
    int*   ctr1  = (int*)  symaddr(g_ctr1);
    int*   ctr2  = (int*)  symaddr(g_ctr2);

    cudaFuncSetAttribute((const void*)gemm_dual7<IND, H1, 128, 16>,
                         cudaFuncAttributeMaxDynamicSharedMemorySize, 33280);
    cudaFuncSetAttribute((const void*)gemm_dual7<H1, H2, 64, 32>,
                         cudaFuncAttributeMaxDynamicSharedMemorySize, 41472);
    cudaFuncSetAttribute((const void*)pool_kernel<NPG, K1, true>,
                         cudaFuncAttributeMaxDynamicSharedMemorySize, POOL1_SMEM);
    cudaFuncSetAttribute((const void*)pool_kernel<K1, K2, false>,
                         cudaFuncAttributeMaxDynamicSharedMemorySize, POOL2_SMEM);

    // ---- zero-fill (all up front) ----
    cudaMemsetAsync(z1, 0, sizeof(float)*Z1_FLOATS);
    cudaMemsetAsync(z2, 0, sizeof(float)*Z2_FLOATS);
    cudaMemsetAsync(map1, 0xFF, sizeof(int)*Nn);   // -1

    // ---- stage 1 ----
    agg_kernel<IND><<<AGG_BLOCKS, 256>>>(src, tgt, x, agg1, cnt1, Ee);
    gemm_dual7<IND, H1, 128, 16><<<Nn/128, 256, 33280>>>(
        agg1, cnt1, x, W1l, W1r, b1l, pre1,
        bnacc1, ctr1, bn1g, bn1b, scale, shift, 1.f/(float)Nn);
    bnad_kernel<H1><<<Nn/8, 256>>>(pre1, scale, shift, p1Wrel, p1Wroot, rrel, rroot, Nn);
    escore_kernel<false><<<AGG_BLOCKS, 256>>>(src, tgt, rrel, sseg1);
    pool_kernel<NPG, K1, true><<<Bg, 1024, POOL1_SMEM>>>(
        sseg1, rroot, p1brel, perm1, tanh1, map1);
    scatter_kernel<<<GATHER_BLOCKS + REMAP_BLOCKS, 256>>>(
        pre1, perm1, scale, shift, tanh1, h1new, src, tgt, map1, src2, tgt2);

    // ---- stage 2 ----
    agg_kernel<H1><<<AGG_BLOCKS, 256>>>(src2, tgt2, h1new, agg2, cnt2, Ee);
    gemm_dual7<H1, H2, 64, 32><<<N1/64, 256, 41472>>>(
        agg2, cnt2, h1new, W2l, W2r, b2l, pre2,
        bnacc2, ctr2, bn2g, bn2b, scale, shift, 1.f/(float)N1);
    bnad_kernel<H2><<<N1/8, 256>>>(pre2, scale, shift, p2Wrel, p2Wroot, rrel, rroot, N1);
    escore_kernel<true><<<AGG_BLOCKS, 256>>>(src2, tgt2, rrel, sseg2);
    pool_kernel<K1, K2, false><<<Bg, 1024, POOL2_SMEM>>>(
        sseg2, rroot, p2brel, perm2, tanh2, nullptr);

    // ---- readout ----
    final_part1<<<Bg*8, 256>>>(pre2, perm2, scale, shift, tanh2, gacc);
    final_part2<<<Bg, 256>>>(gacc, Wlin, blin, out);

    (void)in_sizes; (void)n_in; (void)out_size;
}